// round 2
// baseline (speedup 1.0000x reference)
#include <cuda_runtime.h>
#include <cuda_bf16.h>

// B=8, N=1024, F=320, H=5, D=64, packed QK cols=640
// scale=0.125, TEMP=0.3, NEG_FILL=-1e-7, keep top N/6+1=171 per row

#define BATCH 8
#define SEQ   1024
#define FDIM  320
#define PACK  640

// ---------------- scratch ----------------
__device__ __align__(16) float g_Q [BATCH * SEQ * FDIM];
__device__ __align__(16) float g_K [BATCH * SEQ * FDIM];
__device__ __align__(16) float g_hW[BATCH * SEQ * FDIM];
__device__ __align__(16) float g_at[BATCH * SEQ * SEQ];

// ---------------- f32x2 helpers ----------------
__device__ __forceinline__ void ffma2(unsigned long long& acc,
                                      unsigned long long a,
                                      unsigned long long b) {
    asm("fma.rn.f32x2 %0, %1, %2, %0;" : "+l"(acc) : "l"(a), "l"(b));
}
__device__ __forceinline__ unsigned long long dup2(float x) {
    unsigned long long r;
    asm("mov.b64 %0, {%1, %1};" : "=l"(r) : "r"(__float_as_uint(x)));
    return r;
}
__device__ __forceinline__ void unpack2(unsigned long long p, float& lo, float& hi) {
    unsigned int a, b;
    asm("mov.b64 {%0, %1}, %2;" : "=r"(a), "=r"(b) : "l"(p));
    lo = __uint_as_float(a);
    hi = __uint_as_float(b);
}

// ---------------- FFMA2 SGEMM ----------------
// C[m,n] = alpha * sum_k A[m,k]*B(k,n) (+bias[n])
// TRANSB: B(k,n) = B[n*ldb+k].  SPLIT: scatter even/odd cols to Qo/Ko (+bias first).
// 8x8 per-thread microtile; accumulators packed in pairs along M (f32x2).
template<int BM, int BN, bool TRANSB, bool SPLIT>
__global__ __launch_bounds__((BM/8)*(BN/8), ((BM/8)*(BN/8)==256) ? 2 : 4)
void sgemm2(const float* __restrict__ A, int lda, long long sA,
            const float* __restrict__ B, int ldb, long long sB,
            float* __restrict__ C, int ldc, long long sC,
            const float* __restrict__ bias, int K, float alpha,
            float* __restrict__ Qo, float* __restrict__ Ko, int ldq)
{
    constexpr int BK = 16;
    constexpr int TX = BN / 8;
    constexpr int TY = BM / 8;
    constexpr int NT = TX * TY;
    constexpr int ALD = BM + 4;     // (BM+4)*4B keeps rows 16B-aligned
    constexpr int BLD = BN + 4;

    __shared__ __align__(16) float As[BK * ALD];
    __shared__ __align__(16) float Bs[BK * BLD];

    const int bz = blockIdx.z;
    const float* Ab = A + (long long)bz * sA + (long long)blockIdx.y * BM * lda;
    const float* Bb;
    if (TRANSB) Bb = B + (long long)bz * sB + (long long)blockIdx.x * BN * ldb;
    else        Bb = B + (long long)bz * sB + (long long)blockIdx.x * BN;

    const int tid = threadIdx.x;
    const int tx = tid % TX;
    const int ty = tid / TX;

    unsigned long long acc[4][8];
    #pragma unroll
    for (int i = 0; i < 4; i++)
        #pragma unroll
        for (int j = 0; j < 8; j++) acc[i][j] = 0ull;

    for (int k0 = 0; k0 < K; k0 += BK) {
        // A tile (BM x BK) -> As[k][m] transposed
        constexpr int AF4 = BM * BK / 4;
        #pragma unroll
        for (int it = 0; it < AF4 / NT; it++) {
            int q = tid + it * NT;
            int m  = q >> 2;
            int k4 = (q & 3) << 2;
            float4 v = *(const float4*)(Ab + (long long)m * lda + k0 + k4);
            As[(k4 + 0) * ALD + m] = v.x;
            As[(k4 + 1) * ALD + m] = v.y;
            As[(k4 + 2) * ALD + m] = v.z;
            As[(k4 + 3) * ALD + m] = v.w;
        }
        // B tile -> Bs[k][n]
        if (!TRANSB) {
            constexpr int BF4 = BK * BN / 4;
            #pragma unroll
            for (int it = 0; it < BF4 / NT; it++) {
                int q = tid + it * NT;
                int k  = q / (BN / 4);
                int n4 = (q % (BN / 4)) << 2;
                *(float4*)(Bs + k * BLD + n4) =
                    *(const float4*)(Bb + (long long)(k0 + k) * ldb + n4);
            }
        } else {
            constexpr int BF4 = BN * BK / 4;
            #pragma unroll
            for (int it = 0; it < BF4 / NT; it++) {
                int q = tid + it * NT;
                int n  = q >> 2;
                int k4 = (q & 3) << 2;
                float4 v = *(const float4*)(Bb + (long long)n * ldb + k0 + k4);
                Bs[(k4 + 0) * BLD + n] = v.x;
                Bs[(k4 + 1) * BLD + n] = v.y;
                Bs[(k4 + 2) * BLD + n] = v.z;
                Bs[(k4 + 3) * BLD + n] = v.w;
            }
        }
        __syncthreads();

        #pragma unroll
        for (int kk = 0; kk < BK; kk++) {
            // 4 M-pairs, directly 64-bit from transposed As
            ulonglong2 a01 = *(const ulonglong2*)(As + kk * ALD + ty * 8);
            ulonglong2 a23 = *(const ulonglong2*)(As + kk * ALD + ty * 8 + 4);
            unsigned long long ap[4] = {a01.x, a01.y, a23.x, a23.y};
            float4 b0 = *(const float4*)(Bs + kk * BLD + tx * 8);
            float4 b1 = *(const float4*)(Bs + kk * BLD + tx * 8 + 4);
            float bv[8] = {b0.x, b0.y, b0.z, b0.w, b1.x, b1.y, b1.z, b1.w};
            #pragma unroll
            for (int j = 0; j < 8; j++) {
                unsigned long long bb = dup2(bv[j]);
                #pragma unroll
                for (int i = 0; i < 4; i++)
                    ffma2(acc[i][j], ap[i], bb);
            }
        }
        __syncthreads();
    }

    // ---------------- epilogue ----------------
    const int n0 = tx * 8;                  // tile-local col base (even)
    float bvals[8];
    #pragma unroll
    for (int j = 0; j < 8; j++) bvals[j] = 0.f;
    if (bias) {
        float4 t0 = *(const float4*)(bias + (long long)blockIdx.x * BN + n0);
        float4 t1 = *(const float4*)(bias + (long long)blockIdx.x * BN + n0 + 4);
        bvals[0]=t0.x; bvals[1]=t0.y; bvals[2]=t0.z; bvals[3]=t0.w;
        bvals[4]=t1.x; bvals[5]=t1.y; bvals[6]=t1.z; bvals[7]=t1.w;
    }

    if (SPLIT) {
        // packed cols: even -> Q, odd -> K ; f0 = (bx*BN + n0)/2
        const long long f0 = ((long long)blockIdx.x * BN + n0) >> 1;
        #pragma unroll
        for (int i = 0; i < 4; i++) {
            float r0[8], r1[8];
            #pragma unroll
            for (int j = 0; j < 8; j++) {
                unpack2(acc[i][j], r0[j], r1[j]);
                r0[j] = r0[j] * alpha + bvals[j];
                r1[j] = r1[j] * alpha + bvals[j];
            }
            long long m = (long long)blockIdx.y * BM + ty * 8 + 2 * i;
            float4 q0 = make_float4(r0[0], r0[2], r0[4], r0[6]);
            float4 k0v = make_float4(r0[1], r0[3], r0[5], r0[7]);
            float4 q1 = make_float4(r1[0], r1[2], r1[4], r1[6]);
            float4 k1v = make_float4(r1[1], r1[3], r1[5], r1[7]);
            *(float4*)(Qo + m * ldq + f0)       = q0;
            *(float4*)(Ko + m * ldq + f0)       = k0v;
            *(float4*)(Qo + (m + 1) * ldq + f0) = q1;
            *(float4*)(Ko + (m + 1) * ldq + f0) = k1v;
        }
    } else {
        float* Cb = C + (long long)bz * sC + (long long)blockIdx.y * BM * ldc
                      + (long long)blockIdx.x * BN;
        #pragma unroll
        for (int i = 0; i < 4; i++) {
            float r0[8], r1[8];
            #pragma unroll
            for (int j = 0; j < 8; j++) {
                unpack2(acc[i][j], r0[j], r1[j]);
                r0[j] = r0[j] * alpha + bvals[j];
                r1[j] = r1[j] * alpha + bvals[j];
            }
            int m = ty * 8 + 2 * i;
            *(float4*)(Cb + (long long)m * ldc + n0)           = make_float4(r0[0], r0[1], r0[2], r0[3]);
            *(float4*)(Cb + (long long)m * ldc + n0 + 4)       = make_float4(r0[4], r0[5], r0[6], r0[7]);
            *(float4*)(Cb + (long long)(m + 1) * ldc + n0)     = make_float4(r1[0], r1[1], r1[2], r1[3]);
            *(float4*)(Cb + (long long)(m + 1) * ldc + n0 + 4) = make_float4(r1[4], r1[5], r1[6], r1[7]);
        }
    }
}

// ---------------- top-k threshold + masked softmax (in place) ----------------
__global__ __launch_bounds__(256) void mask_softmax_kernel(float* __restrict__ at)
{
    __shared__ float xbuf[SEQ];
    __shared__ float sbuf[SEQ];
    __shared__ float red[8];

    const int tid = threadIdx.x;
    float* row = at + (long long)blockIdx.x * SEQ;

    #pragma unroll
    for (int c = 0; c < 4; c++) {
        float v = row[tid + 256 * c];
        xbuf[tid + 256 * c] = v;
        sbuf[tid + 256 * c] = v;
    }
    __syncthreads();

    for (int k = 2; k <= SEQ; k <<= 1) {
        for (int j = k >> 1; j > 0; j >>= 1) {
            #pragma unroll
            for (int c = 0; c < 4; c++) {
                int i   = tid + 256 * c;
                int ixj = i ^ j;
                if (ixj > i) {
                    float a = sbuf[i], b = sbuf[ixj];
                    bool up = ((i & k) == 0);
                    if ((a > b) == up) { sbuf[i] = b; sbuf[ixj] = a; }
                }
            }
            __syncthreads();
        }
    }

    const float thr = sbuf[SEQ - (SEQ / 6 + 1)];   // 171st largest

    float adj[4];
    float lmax = -3.402823466e38f;
    #pragma unroll
    for (int c = 0; c < 4; c++) {
        float v = xbuf[tid + 256 * c];
        v = (v < thr) ? -1e-7f : v;
        adj[c] = v;
        lmax = fmaxf(lmax, v);
    }
    #pragma unroll
    for (int o = 16; o > 0; o >>= 1)
        lmax = fmaxf(lmax, __shfl_xor_sync(0xFFFFFFFFu, lmax, o));
    if ((tid & 31) == 0) red[tid >> 5] = lmax;
    __syncthreads();
    if (tid < 32) {
        float m = (tid < 8) ? red[tid] : -3.402823466e38f;
        #pragma unroll
        for (int o = 4; o > 0; o >>= 1)
            m = fmaxf(m, __shfl_xor_sync(0xFFFFFFFFu, m, o));
        if (tid == 0) red[0] = m;
    }
    __syncthreads();
    const float m = red[0];
    __syncthreads();

    const float inv_t = 1.0f / 0.3f;
    float e[4];
    float lsum = 0.f;
    #pragma unroll
    for (int c = 0; c < 4; c++) {
        e[c] = __expf((adj[c] - m) * inv_t);
        lsum += e[c];
    }
    #pragma unroll
    for (int o = 16; o > 0; o >>= 1)
        lsum += __shfl_xor_sync(0xFFFFFFFFu, lsum, o);
    if ((tid & 31) == 0) red[tid >> 5] = lsum;
    __syncthreads();
    if (tid < 32) {
        float s = (tid < 8) ? red[tid] : 0.f;
        #pragma unroll
        for (int o = 4; o > 0; o >>= 1)
            s += __shfl_xor_sync(0xFFFFFFFFu, s, o);
        if (tid == 0) red[0] = s;
    }
    __syncthreads();
    const float inv_sum = 1.0f / red[0];

    #pragma unroll
    for (int c = 0; c < 4; c++)
        row[tid + 256 * c] = e[c] * inv_sum;
}

// ---------------- launch ----------------
extern "C" void kernel_launch(void* const* d_in, const int* in_sizes, int n_in,
                              void* d_out, int out_size)
{
    const float* h      = (const float*)d_in[0];   // [8,1024,320]
    const float* Wqk    = (const float*)d_in[1];   // [320,640]
    const float* bqk    = (const float*)d_in[2];   // [640]
    const float* weight = (const float*)d_in[3];   // [320,320]
    const float* bias   = (const float*)d_in[4];   // [320]
    float* out = (float*)d_out;                    // [8,1024,320]

    float *Q, *K, *hW, *at;
    cudaGetSymbolAddress((void**)&Q,  g_Q);
    cudaGetSymbolAddress((void**)&K,  g_K);
    cudaGetSymbolAddress((void**)&hW, g_hW);
    cudaGetSymbolAddress((void**)&at, g_at);

    const long long NF = (long long)SEQ * FDIM;
    const long long NN = (long long)SEQ * SEQ;

    // 1) packed QK projection fused with even/odd split: Q,K <- h @ Wqk + bqk
    sgemm2<128, 128, false, true><<<dim3(PACK / 128, (BATCH * SEQ) / 128, 1), 256>>>(
        h, FDIM, 0, Wqk, PACK, 0, nullptr, 0, 0, bqk, FDIM, 1.0f, Q, K, FDIM);

    // 2) hW = h @ weight
    sgemm2<128, 64, false, false><<<dim3(FDIM / 64, (BATCH * SEQ) / 128, 1), 128>>>(
        h, FDIM, 0, weight, FDIM, 0, hW, FDIM, 0, nullptr, FDIM, 1.0f,
        nullptr, nullptr, 0);

    // 3) at[b] = 0.125 * Q[b] @ K[b]^T
    sgemm2<128, 128, true, false><<<dim3(SEQ / 128, SEQ / 128, BATCH), 256>>>(
        Q, FDIM, NF, K, FDIM, NF, at, SEQ, NN, nullptr, FDIM, 0.125f,
        nullptr, nullptr, 0);

    // 4) top-171 threshold mask + softmax(x/0.3)
    mask_softmax_kernel<<<BATCH * SEQ, 256>>>(at);

    // 5) out[b] = attn[b] @ hW[b] + bias
    sgemm2<128, 64, false, false><<<dim3(FDIM / 64, SEQ / 128, BATCH), 128>>>(
        at, SEQ, NN, hW, FDIM, NF, out, FDIM, NF, bias, SEQ, 1.0f,
        nullptr, nullptr, 0);
}

// round 3
// speedup vs baseline: 1.3202x; 1.3202x over previous
#include <cuda_runtime.h>
#include <cuda_bf16.h>

// B=8, N=1024, F=320, H=5, D=64, packed QK cols=640
// scale=0.125, TEMP=0.3, NEG_FILL=-1e-7, keep top N/6+1=171 per row

#define BATCH 8
#define SEQ   1024
#define FDIM  320
#define PACK  640
#define KSEL  171   // SEQ/6 + 1

// ---------------- scratch ----------------
__device__ __align__(16) float g_Q [BATCH * SEQ * FDIM];
__device__ __align__(16) float g_K [BATCH * SEQ * FDIM];
__device__ __align__(16) float g_hW[BATCH * SEQ * FDIM];
__device__ __align__(16) float g_at[BATCH * SEQ * SEQ];

// ---------------- f32x2 helpers ----------------
__device__ __forceinline__ void ffma2(unsigned long long& acc,
                                      unsigned long long a,
                                      unsigned long long b) {
    asm("fma.rn.f32x2 %0, %1, %2, %0;" : "+l"(acc) : "l"(a), "l"(b));
}
__device__ __forceinline__ unsigned long long dup2(float x) {
    unsigned long long r;
    asm("mov.b64 %0, {%1, %1};" : "=l"(r) : "r"(__float_as_uint(x)));
    return r;
}
__device__ __forceinline__ void unpack2(unsigned long long p, float& lo, float& hi) {
    unsigned int a, b;
    asm("mov.b64 {%0, %1}, %2;" : "=r"(a), "=r"(b) : "l"(p));
    lo = __uint_as_float(a);
    hi = __uint_as_float(b);
}

// ---------------- FFMA2 SGEMM (unchanged from R2) ----------------
template<int BM, int BN, bool TRANSB, bool SPLIT>
__global__ __launch_bounds__((BM/8)*(BN/8), ((BM/8)*(BN/8)==256) ? 2 : 4)
void sgemm2(const float* __restrict__ A, int lda, long long sA,
            const float* __restrict__ B, int ldb, long long sB,
            float* __restrict__ C, int ldc, long long sC,
            const float* __restrict__ bias, int K, float alpha,
            float* __restrict__ Qo, float* __restrict__ Ko, int ldq)
{
    constexpr int BK = 16;
    constexpr int TX = BN / 8;
    constexpr int TY = BM / 8;
    constexpr int NT = TX * TY;
    constexpr int ALD = BM + 4;
    constexpr int BLD = BN + 4;

    __shared__ __align__(16) float As[BK * ALD];
    __shared__ __align__(16) float Bs[BK * BLD];

    const int bz = blockIdx.z;
    const float* Ab = A + (long long)bz * sA + (long long)blockIdx.y * BM * lda;
    const float* Bb;
    if (TRANSB) Bb = B + (long long)bz * sB + (long long)blockIdx.x * BN * ldb;
    else        Bb = B + (long long)bz * sB + (long long)blockIdx.x * BN;

    const int tid = threadIdx.x;
    const int tx = tid % TX;
    const int ty = tid / TX;

    unsigned long long acc[4][8];
    #pragma unroll
    for (int i = 0; i < 4; i++)
        #pragma unroll
        for (int j = 0; j < 8; j++) acc[i][j] = 0ull;

    for (int k0 = 0; k0 < K; k0 += BK) {
        constexpr int AF4 = BM * BK / 4;
        #pragma unroll
        for (int it = 0; it < AF4 / NT; it++) {
            int q = tid + it * NT;
            int m  = q >> 2;
            int k4 = (q & 3) << 2;
            float4 v = *(const float4*)(Ab + (long long)m * lda + k0 + k4);
            As[(k4 + 0) * ALD + m] = v.x;
            As[(k4 + 1) * ALD + m] = v.y;
            As[(k4 + 2) * ALD + m] = v.z;
            As[(k4 + 3) * ALD + m] = v.w;
        }
        if (!TRANSB) {
            constexpr int BF4 = BK * BN / 4;
            #pragma unroll
            for (int it = 0; it < BF4 / NT; it++) {
                int q = tid + it * NT;
                int k  = q / (BN / 4);
                int n4 = (q % (BN / 4)) << 2;
                *(float4*)(Bs + k * BLD + n4) =
                    *(const float4*)(Bb + (long long)(k0 + k) * ldb + n4);
            }
        } else {
            constexpr int BF4 = BN * BK / 4;
            #pragma unroll
            for (int it = 0; it < BF4 / NT; it++) {
                int q = tid + it * NT;
                int n  = q >> 2;
                int k4 = (q & 3) << 2;
                float4 v = *(const float4*)(Bb + (long long)n * ldb + k0 + k4);
                Bs[(k4 + 0) * BLD + n] = v.x;
                Bs[(k4 + 1) * BLD + n] = v.y;
                Bs[(k4 + 2) * BLD + n] = v.z;
                Bs[(k4 + 3) * BLD + n] = v.w;
            }
        }
        __syncthreads();

        #pragma unroll
        for (int kk = 0; kk < BK; kk++) {
            ulonglong2 a01 = *(const ulonglong2*)(As + kk * ALD + ty * 8);
            ulonglong2 a23 = *(const ulonglong2*)(As + kk * ALD + ty * 8 + 4);
            unsigned long long ap[4] = {a01.x, a01.y, a23.x, a23.y};
            float4 b0 = *(const float4*)(Bs + kk * BLD + tx * 8);
            float4 b1 = *(const float4*)(Bs + kk * BLD + tx * 8 + 4);
            float bv[8] = {b0.x, b0.y, b0.z, b0.w, b1.x, b1.y, b1.z, b1.w};
            #pragma unroll
            for (int j = 0; j < 8; j++) {
                unsigned long long bb = dup2(bv[j]);
                #pragma unroll
                for (int i = 0; i < 4; i++)
                    ffma2(acc[i][j], ap[i], bb);
            }
        }
        __syncthreads();
    }

    const int n0 = tx * 8;
    float bvals[8];
    #pragma unroll
    for (int j = 0; j < 8; j++) bvals[j] = 0.f;
    if (bias) {
        float4 t0 = *(const float4*)(bias + (long long)blockIdx.x * BN + n0);
        float4 t1 = *(const float4*)(bias + (long long)blockIdx.x * BN + n0 + 4);
        bvals[0]=t0.x; bvals[1]=t0.y; bvals[2]=t0.z; bvals[3]=t0.w;
        bvals[4]=t1.x; bvals[5]=t1.y; bvals[6]=t1.z; bvals[7]=t1.w;
    }

    if (SPLIT) {
        const long long f0 = ((long long)blockIdx.x * BN + n0) >> 1;
        #pragma unroll
        for (int i = 0; i < 4; i++) {
            float r0[8], r1[8];
            #pragma unroll
            for (int j = 0; j < 8; j++) {
                unpack2(acc[i][j], r0[j], r1[j]);
                r0[j] = r0[j] * alpha + bvals[j];
                r1[j] = r1[j] * alpha + bvals[j];
            }
            long long m = (long long)blockIdx.y * BM + ty * 8 + 2 * i;
            *(float4*)(Qo + m * ldq + f0)       = make_float4(r0[0], r0[2], r0[4], r0[6]);
            *(float4*)(Ko + m * ldq + f0)       = make_float4(r0[1], r0[3], r0[5], r0[7]);
            *(float4*)(Qo + (m + 1) * ldq + f0) = make_float4(r1[0], r1[2], r1[4], r1[6]);
            *(float4*)(Ko + (m + 1) * ldq + f0) = make_float4(r1[1], r1[3], r1[5], r1[7]);
        }
    } else {
        float* Cb = C + (long long)bz * sC + (long long)blockIdx.y * BM * ldc
                      + (long long)blockIdx.x * BN;
        #pragma unroll
        for (int i = 0; i < 4; i++) {
            float r0[8], r1[8];
            #pragma unroll
            for (int j = 0; j < 8; j++) {
                unpack2(acc[i][j], r0[j], r1[j]);
                r0[j] = r0[j] * alpha + bvals[j];
                r1[j] = r1[j] * alpha + bvals[j];
            }
            int m = ty * 8 + 2 * i;
            *(float4*)(Cb + (long long)m * ldc + n0)           = make_float4(r0[0], r0[1], r0[2], r0[3]);
            *(float4*)(Cb + (long long)m * ldc + n0 + 4)       = make_float4(r0[4], r0[5], r0[6], r0[7]);
            *(float4*)(Cb + (long long)(m + 1) * ldc + n0)     = make_float4(r1[0], r1[1], r1[2], r1[3]);
            *(float4*)(Cb + (long long)(m + 1) * ldc + n0 + 4) = make_float4(r1[4], r1[5], r1[6], r1[7]);
        }
    }
}

// ---------------- radix-select top-k threshold + masked softmax -------------
// One block (256 threads) per row of 1024. Values held in registers.
// Exact 171st-largest via 4 rounds of 8-bit radix select on order-preserving
// uint keys, then mask + softmax.
__global__ __launch_bounds__(256) void mask_softmax_kernel(float* __restrict__ at)
{
    __shared__ unsigned int hist[256];
    __shared__ float redf[8];
    __shared__ unsigned int s_bin, s_k;

    const int tid = threadIdx.x;
    float* row = at + (long long)blockIdx.x * SEQ;

    // load row (coalesced float4 per thread), build sortable keys, row max
    float4 vv = *(const float4*)(row + tid * 4);
    float v[4] = {vv.x, vv.y, vv.z, vv.w};
    unsigned int u[4];
    float lmax = -3.402823466e38f;
    #pragma unroll
    for (int c = 0; c < 4; c++) {
        unsigned int b = __float_as_uint(v[c]);
        u[c] = (b & 0x80000000u) ? ~b : (b | 0x80000000u);   // ascending order
        lmax = fmaxf(lmax, v[c]);
    }

    // block max reduce
    #pragma unroll
    for (int o = 16; o > 0; o >>= 1)
        lmax = fmaxf(lmax, __shfl_xor_sync(0xFFFFFFFFu, lmax, o));
    if ((tid & 31) == 0) redf[tid >> 5] = lmax;
    __syncthreads();
    if (tid < 32) {
        float m = (tid < 8) ? redf[tid] : -3.402823466e38f;
        #pragma unroll
        for (int o = 4; o > 0; o >>= 1)
            m = fmaxf(m, __shfl_xor_sync(0xFFFFFFFFu, m, o));
        if (tid == 0) redf[0] = m;
    }
    __syncthreads();
    const float m = redf[0];

    // ---- 4-round radix select for the KSEL-th largest key ----
    unsigned int prefix = 0;
    unsigned int k = KSEL;
    #pragma unroll
    for (int shift = 24; shift >= 0; shift -= 8) {
        hist[tid] = 0;
        __syncthreads();
        const unsigned int himask =
            (shift == 24) ? 0u : (0xFFFFFFFFu << (shift + 8));
        #pragma unroll
        for (int c = 0; c < 4; c++)
            if ((u[c] & himask) == prefix)
                atomicAdd(&hist[(u[c] >> shift) & 255u], 1u);
        __syncthreads();
        if (tid < 32) {
            unsigned int h[8], tot = 0;
            #pragma unroll
            for (int i = 0; i < 8; i++) { h[i] = hist[tid * 8 + i]; tot += h[i]; }
            // inclusive suffix-sum over lanes (lane covers bins [8L, 8L+8))
            unsigned int s = tot;
            #pragma unroll
            for (int o = 1; o < 32; o <<= 1) {
                unsigned int x = __shfl_down_sync(0xFFFFFFFFu, s, o);
                if (tid + o < 32) s += x;
            }
            unsigned int run = s - tot;  // # elements strictly above this lane's bins
            #pragma unroll
            for (int i = 7; i >= 0; i--) {
                unsigned int greater = run;     // # elements in bins > this bin
                run += h[i];
                if (greater < k && k <= run) {  // k-th largest lands in this bin
                    s_bin = tid * 8 + i;
                    s_k   = k - greater;
                }
            }
        }
        __syncthreads();
        prefix |= s_bin << shift;
        k = s_k;
    }
    const unsigned int thr_u = prefix;   // sortable key of the 171st largest

    // ---- mask + softmax (values still in regs) ----
    const float inv_t = 1.0f / 0.3f;
    float e[4];
    float lsum = 0.f;
    #pragma unroll
    for (int c = 0; c < 4; c++) {
        float adj = (u[c] >= thr_u) ? v[c] : -1e-7f;
        e[c] = __expf((adj - m) * inv_t);
        lsum += e[c];
    }
    #pragma unroll
    for (int o = 16; o > 0; o >>= 1)
        lsum += __shfl_xor_sync(0xFFFFFFFFu, lsum, o);
    if ((tid & 31) == 0) redf[tid >> 5] = lsum;
    __syncthreads();
    if (tid < 32) {
        float s = (tid < 8) ? redf[tid] : 0.f;
        #pragma unroll
        for (int o = 4; o > 0; o >>= 1)
            s += __shfl_xor_sync(0xFFFFFFFFu, s, o);
        if (tid == 0) redf[0] = s;
    }
    __syncthreads();
    const float inv_sum = 1.0f / redf[0];

    *(float4*)(row + tid * 4) = make_float4(e[0] * inv_sum, e[1] * inv_sum,
                                            e[2] * inv_sum, e[3] * inv_sum);
}

// ---------------- launch ----------------
extern "C" void kernel_launch(void* const* d_in, const int* in_sizes, int n_in,
                              void* d_out, int out_size)
{
    const float* h      = (const float*)d_in[0];   // [8,1024,320]
    const float* Wqk    = (const float*)d_in[1];   // [320,640]
    const float* bqk    = (const float*)d_in[2];   // [640]
    const float* weight = (const float*)d_in[3];   // [320,320]
    const float* bias   = (const float*)d_in[4];   // [320]
    float* out = (float*)d_out;                    // [8,1024,320]

    float *Q, *K, *hW, *at;
    cudaGetSymbolAddress((void**)&Q,  g_Q);
    cudaGetSymbolAddress((void**)&K,  g_K);
    cudaGetSymbolAddress((void**)&hW, g_hW);
    cudaGetSymbolAddress((void**)&at, g_at);

    const long long NF = (long long)SEQ * FDIM;
    const long long NN = (long long)SEQ * SEQ;

    // 1) packed QK projection fused with even/odd split: Q,K <- h @ Wqk + bqk
    sgemm2<128, 128, false, true><<<dim3(PACK / 128, (BATCH * SEQ) / 128, 1), 256>>>(
        h, FDIM, 0, Wqk, PACK, 0, nullptr, 0, 0, bqk, FDIM, 1.0f, Q, K, FDIM);

    // 2) hW = h @ weight
    sgemm2<128, 64, false, false><<<dim3(FDIM / 64, (BATCH * SEQ) / 128, 1), 128>>>(
        h, FDIM, 0, weight, FDIM, 0, hW, FDIM, 0, nullptr, FDIM, 1.0f,
        nullptr, nullptr, 0);

    // 3) at[b] = 0.125 * Q[b] @ K[b]^T
    sgemm2<128, 128, true, false><<<dim3(SEQ / 128, SEQ / 128, BATCH), 256>>>(
        Q, FDIM, NF, K, FDIM, NF, at, SEQ, NN, nullptr, FDIM, 0.125f,
        nullptr, nullptr, 0);

    // 4) exact top-171 threshold (radix select) + masked softmax(x/0.3)
    mask_softmax_kernel<<<BATCH * SEQ, 256>>>(at);

    // 5) out[b] = attn[b] @ hW[b] + bias
    sgemm2<128, 64, false, false><<<dim3(FDIM / 64, SEQ / 128, BATCH), 128>>>(
        at, SEQ, NN, hW, FDIM, NF, out, FDIM, NF, bias, SEQ, 1.0f,
        nullptr, nullptr, 0);
}

// round 5
// speedup vs baseline: 2.1845x; 1.6546x over previous
#include <cuda_runtime.h>
#include <cuda_bf16.h>

// B=8, N=1024, F=320, H=5, D=64, packed QK cols=640
// scale=0.125, TEMP=0.3, NEG_FILL=-1e-7, keep top N/6+1=171 per row

#define BATCH 8
#define SEQ   1024
#define FDIM  320
#define PACK  640
#define KSEL  171

// ---------------- scratch (device globals) ----------------
__device__ __align__(16) __nv_bfloat16 g_hh  [BATCH * SEQ * FDIM];
__device__ __align__(16) __nv_bfloat16 g_hl  [BATCH * SEQ * FDIM];
__device__ __align__(16) __nv_bfloat16 g_wqkTh[PACK * FDIM];
__device__ __align__(16) __nv_bfloat16 g_wqkTl[PACK * FDIM];
__device__ __align__(16) __nv_bfloat16 g_wTh [FDIM * FDIM];
__device__ __align__(16) __nv_bfloat16 g_wTl [FDIM * FDIM];
__device__ __align__(16) __nv_bfloat16 g_Qh  [BATCH * SEQ * FDIM];
__device__ __align__(16) __nv_bfloat16 g_Ql  [BATCH * SEQ * FDIM];
__device__ __align__(16) __nv_bfloat16 g_Kh  [BATCH * SEQ * FDIM];
__device__ __align__(16) __nv_bfloat16 g_Kl  [BATCH * SEQ * FDIM];
__device__ __align__(16) __nv_bfloat16 g_hWTh[BATCH * FDIM * SEQ];
__device__ __align__(16) __nv_bfloat16 g_hWTl[BATCH * FDIM * SEQ];
__device__ __align__(16) float         g_at  [BATCH * SEQ * SEQ];
__device__ __align__(16) __nv_bfloat16 g_Ph  [BATCH * SEQ * SEQ];
__device__ __align__(16) __nv_bfloat16 g_Pl  [BATCH * SEQ * SEQ];

// ---------------- helpers ----------------
__device__ __forceinline__ unsigned smem_u32(const void* p) {
    unsigned a;
    asm("{ .reg .u64 t; cvta.to.shared.u64 t, %1; cvt.u32.u64 %0, t; }"
        : "=r"(a) : "l"(p));
    return a;
}
__device__ __forceinline__ void cpa16(unsigned s, const void* g) {
    asm volatile("cp.async.cg.shared.global [%0], [%1], 16;" :: "r"(s), "l"(g));
}
__device__ __forceinline__ __nv_bfloat16 bf_hi(float v) { return __float2bfloat16_rn(v); }
__device__ __forceinline__ __nv_bfloat16 bf_lo(float v, __nv_bfloat16 h) {
    return __float2bfloat16_rn(v - __bfloat162float(h));
}

__device__ __forceinline__ void mma16816(float* d, const unsigned* a, const unsigned* b) {
    asm volatile(
        "mma.sync.aligned.m16n8k16.row.col.f32.bf16.bf16.f32 "
        "{%0,%1,%2,%3}, {%4,%5,%6,%7}, {%8,%9}, {%0,%1,%2,%3};"
        : "+f"(d[0]), "+f"(d[1]), "+f"(d[2]), "+f"(d[3])
        : "r"(a[0]), "r"(a[1]), "r"(a[2]), "r"(a[3]), "r"(b[0]), "r"(b[1]));
}

#define SLD 40   // smem row pitch in bf16 (80B = 20 banks -> conflict-free frags)

__device__ __forceinline__ void ldA(unsigned a[4], const __nv_bfloat16* As,
                                    int row0, int kk, int g, int t) {
    const __nv_bfloat16* p = As + (row0 + g) * SLD + kk + 2 * t;
    a[0] = *(const unsigned*)p;
    a[1] = *(const unsigned*)(p + 8 * SLD);
    a[2] = *(const unsigned*)(p + 8);
    a[3] = *(const unsigned*)(p + 8 * SLD + 8);
}
__device__ __forceinline__ void ldB(unsigned b[2], const __nv_bfloat16* Bs,
                                    int n0, int kk, int g, int t) {
    const __nv_bfloat16* p = Bs + (n0 + g) * SLD + kk + 2 * t;
    b[0] = *(const unsigned*)p;
    b[1] = *(const unsigned*)(p + 8);
}

// ---------------- mma.sync split-bf16 GEMM ----------------
// C[m,n] = sum_k A[m,k] * B[n,k]; A,B bf16 (hi,lo) K-major; fp32 acc.
// 3-term: hi*hi + hi*lo + lo*hi.
// EPI: 0 = fp32 C; 1 = proj -> Q/K hi/lo (+bqk, K*0.125);
//      2 = hWT hi/lo (transposed scatter); 3 = fp32 out + bias.
template<int BN, int EPI>
__global__ __launch_bounds__(256, 1) void mm_gemm(
    const __nv_bfloat16* __restrict__ Ah, const __nv_bfloat16* __restrict__ Al,
    long long sA, int lda,
    const __nv_bfloat16* __restrict__ Bh, const __nv_bfloat16* __restrict__ Bl,
    long long sB, int ldb,
    float* __restrict__ Cout, long long sC, int ldc,
    const float* __restrict__ bias,
    __nv_bfloat16* __restrict__ O1h, __nv_bfloat16* __restrict__ O1l,
    __nv_bfloat16* __restrict__ O2h, __nv_bfloat16* __restrict__ O2l,
    int Ktot)
{
    constexpr int WX = (BN == 128) ? 4 : 2;       // warps along N
    constexpr int WM = (BN == 128) ? 64 : 32;     // warp tile M
    constexpr int WN = 32;                         // warp tile N
    constexpr int MT = WM / 16;
    constexpr int NT = WN / 8;
    constexpr int ASZ = 128 * SLD;                 // bf16 elements per matrix
    constexpr int BSZ = BN * SLD;
    constexpr int STAGE = 2 * ASZ + 2 * BSZ;       // elements

    extern __shared__ __nv_bfloat16 smem[];

    const int tid = threadIdx.x;
    const int wid = tid >> 5;
    const int lane = tid & 31;
    const int g = lane >> 2, t = lane & 3;
    const int wy = wid / WX, wx = wid % WX;

    const __nv_bfloat16* Ath = Ah + blockIdx.z * sA + (long long)blockIdx.y * 128 * lda;
    const __nv_bfloat16* Atl = Al + blockIdx.z * sA + (long long)blockIdx.y * 128 * lda;
    const __nv_bfloat16* Bth = Bh + blockIdx.z * sB + (long long)blockIdx.x * BN * ldb;
    const __nv_bfloat16* Btl = Bl + blockIdx.z * sB + (long long)blockIdx.x * BN * ldb;

    const unsigned sb0 = smem_u32(smem);
    const int S = Ktot >> 5;

    auto load_stage = [&](int s) {
        const unsigned sb = sb0 + (s & 1) * STAGE * 2;   // bytes
        const int k0 = s << 5;
        #pragma unroll
        for (int q = tid; q < 512; q += 256) {
            int row = q >> 2, c = q & 3;
            unsigned so = sb + (row * SLD + c * 8) * 2;
            cpa16(so,            Ath + (long long)row * lda + k0 + c * 8);
            cpa16(so + ASZ * 2,  Atl + (long long)row * lda + k0 + c * 8);
        }
        #pragma unroll
        for (int q = tid; q < BN * 4; q += 256) {
            int row = q >> 2, c = q & 3;
            unsigned so = sb + 4 * ASZ + (row * SLD + c * 8) * 2;
            cpa16(so,           Bth + (long long)row * ldb + k0 + c * 8);
            cpa16(so + BSZ * 2, Btl + (long long)row * ldb + k0 + c * 8);
        }
        asm volatile("cp.async.commit_group;" ::: "memory");
    };

    float acc[MT][NT][4];
    #pragma unroll
    for (int i = 0; i < MT; i++)
        #pragma unroll
        for (int j = 0; j < NT; j++)
            #pragma unroll
            for (int r = 0; r < 4; r++) acc[i][j][r] = 0.f;

    load_stage(0);
    for (int s = 0; s < S; s++) {
        if (s + 1 < S) {
            load_stage(s + 1);
            asm volatile("cp.async.wait_group 1;" ::: "memory");
        } else {
            asm volatile("cp.async.wait_group 0;" ::: "memory");
        }
        __syncthreads();

        const __nv_bfloat16* Ahs = smem + (s & 1) * STAGE;
        const __nv_bfloat16* Als = Ahs + ASZ;
        const __nv_bfloat16* Bhs = Ahs + 2 * ASZ;
        const __nv_bfloat16* Bls = Ahs + 2 * ASZ + BSZ;

        #pragma unroll
        for (int kk = 0; kk < 32; kk += 16) {
            unsigned ah[MT][4], al[MT][4], bh[NT][2], bl[NT][2];
            #pragma unroll
            for (int mt = 0; mt < MT; mt++) {
                ldA(ah[mt], Ahs, wy * WM + mt * 16, kk, g, t);
                ldA(al[mt], Als, wy * WM + mt * 16, kk, g, t);
            }
            #pragma unroll
            for (int nt = 0; nt < NT; nt++) {
                ldB(bh[nt], Bhs, wx * WN + nt * 8, kk, g, t);
                ldB(bl[nt], Bls, wx * WN + nt * 8, kk, g, t);
            }
            #pragma unroll
            for (int mt = 0; mt < MT; mt++)
                #pragma unroll
                for (int nt = 0; nt < NT; nt++) {
                    mma16816(acc[mt][nt], ah[mt], bh[nt]);
                    mma16816(acc[mt][nt], ah[mt], bl[nt]);
                    mma16816(acc[mt][nt], al[mt], bh[nt]);
                }
        }
        __syncthreads();
    }

    // ---------------- epilogue ----------------
    #pragma unroll
    for (int mt = 0; mt < MT; mt++) {
        #pragma unroll
        for (int nt = 0; nt < NT; nt++) {
            const float* c = acc[mt][nt];
            const int mloc = wy * WM + mt * 16 + g;          // local row (and +8)
            const int nloc = wx * WN + nt * 8 + 2 * t;       // local col (and +1)
            const long long mg = (long long)blockIdx.y * 128 + mloc;
            const int ng = blockIdx.x * BN + nloc;

            if constexpr (EPI == 0) {
                float* C0 = Cout + blockIdx.z * sC + mg * ldc + ng;
                *(float2*)C0                 = make_float2(c[0], c[1]);
                *(float2*)(C0 + 8LL * ldc)   = make_float2(c[2], c[3]);
            } else if constexpr (EPI == 1) {
                const float b0 = bias[ng], b1 = bias[ng + 1];
                const int f = ng >> 1;
                float q0 = c[0] + b0, k0 = (c[1] + b1) * 0.125f;
                float q1 = c[2] + b0, k1 = (c[3] + b1) * 0.125f;
                long long u0 = mg * FDIM + f;
                long long u1 = (mg + 8) * FDIM + f;
                __nv_bfloat16 h;
                h = bf_hi(q0); O1h[u0] = h; O1l[u0] = bf_lo(q0, h);
                h = bf_hi(k0); O2h[u0] = h; O2l[u0] = bf_lo(k0, h);
                h = bf_hi(q1); O1h[u1] = h; O1l[u1] = bf_lo(q1, h);
                h = bf_hi(k1); O2h[u1] = h; O2l[u1] = bf_lo(k1, h);
            } else if constexpr (EPI == 2) {
                const int b = (int)(mg >> 10);
                const int ml = (int)(mg & 1023);
                long long o = ((long long)b * FDIM + ng) * SEQ + ml;
                __nv_bfloat16 h;
                h = bf_hi(c[0]); O1h[o] = h;            O1l[o] = bf_lo(c[0], h);
                h = bf_hi(c[1]); O1h[o + SEQ] = h;      O1l[o + SEQ] = bf_lo(c[1], h);
                h = bf_hi(c[2]); O1h[o + 8] = h;        O1l[o + 8] = bf_lo(c[2], h);
                h = bf_hi(c[3]); O1h[o + SEQ + 8] = h;  O1l[o + SEQ + 8] = bf_lo(c[3], h);
            } else {
                const float b0 = bias[ng], b1 = bias[ng + 1];
                float* C0 = Cout + (blockIdx.z * (long long)SEQ + mg) * FDIM + ng;
                *(float2*)C0                 = make_float2(c[0] + b0, c[1] + b1);
                *(float2*)(C0 + 8LL * FDIM)  = make_float2(c[2] + b0, c[3] + b1);
            }
        }
    }
}

// ---------------- prep: fp32 -> bf16 hi/lo split ----------------
__global__ void split_kernel(const float* __restrict__ src,
                             __nv_bfloat16* __restrict__ hi,
                             __nv_bfloat16* __restrict__ lo, int n4)
{
    int i = blockIdx.x * blockDim.x + threadIdx.x;
    if (i < n4) {
        float4 v = ((const float4*)src)[i];
        float a[4] = {v.x, v.y, v.z, v.w};
        __nv_bfloat16 h[4], l[4];
        #pragma unroll
        for (int c = 0; c < 4; c++) { h[c] = bf_hi(a[c]); l[c] = bf_lo(a[c], h[c]); }
        ((__nv_bfloat162*)hi)[2 * i]     = __halves2bfloat162(h[0], h[1]);
        ((__nv_bfloat162*)hi)[2 * i + 1] = __halves2bfloat162(h[2], h[3]);
        ((__nv_bfloat162*)lo)[2 * i]     = __halves2bfloat162(l[0], l[1]);
        ((__nv_bfloat162*)lo)[2 * i + 1] = __halves2bfloat162(l[2], l[3]);
    }
}

// ---------------- prep: transpose + split ----------------
__global__ void transpose_split_kernel(const float* __restrict__ src, int R, int C,
                                       __nv_bfloat16* __restrict__ th,
                                       __nv_bfloat16* __restrict__ tl)
{
    __shared__ float tbuf[32][33];
    int x = blockIdx.x * 32 + threadIdx.x;
    int y0 = blockIdx.y * 32;
    #pragma unroll
    for (int j = threadIdx.y; j < 32; j += 8)
        tbuf[j][threadIdx.x] = src[(long long)(y0 + j) * C + x];
    __syncthreads();
    int xo = y0 + threadIdx.x;
    int co = blockIdx.x * 32;
    #pragma unroll
    for (int j = threadIdx.y; j < 32; j += 8) {
        float v = tbuf[threadIdx.x][j];
        __nv_bfloat16 h = bf_hi(v);
        th[(long long)(co + j) * R + xo] = h;
        tl[(long long)(co + j) * R + xo] = bf_lo(v, h);
    }
}

// ---------------- radix-select top-k + masked softmax -> bf16 splits --------
__global__ __launch_bounds__(256) void mask_softmax_kernel(
    const float* __restrict__ at,
    __nv_bfloat16* __restrict__ Ph, __nv_bfloat16* __restrict__ Pl)
{
    __shared__ unsigned hist[256];
    __shared__ float redf[8];
    __shared__ unsigned s_bin, s_k;

    const int tid = threadIdx.x;
    const float* row = at + (long long)blockIdx.x * SEQ;

    float4 vv = *(const float4*)(row + tid * 4);
    float v[4] = {vv.x, vv.y, vv.z, vv.w};
    unsigned u[4];
    float lmax = -3.402823466e38f;
    #pragma unroll
    for (int c = 0; c < 4; c++) {
        unsigned b = __float_as_uint(v[c]);
        u[c] = (b & 0x80000000u) ? ~b : (b | 0x80000000u);
        lmax = fmaxf(lmax, v[c]);
    }
    #pragma unroll
    for (int o = 16; o > 0; o >>= 1)
        lmax = fmaxf(lmax, __shfl_xor_sync(0xFFFFFFFFu, lmax, o));
    if ((tid & 31) == 0) redf[tid >> 5] = lmax;
    __syncthreads();
    if (tid < 32) {
        float m = (tid < 8) ? redf[tid] : -3.402823466e38f;
        #pragma unroll
        for (int o = 4; o > 0; o >>= 1)
            m = fmaxf(m, __shfl_xor_sync(0xFFFFFFFFu, m, o));
        if (tid == 0) redf[0] = m;
    }
    __syncthreads();
    const float m = redf[0];

    unsigned prefix = 0, k = KSEL;
    #pragma unroll
    for (int shift = 24; shift >= 0; shift -= 8) {
        hist[tid] = 0;
        __syncthreads();
        const unsigned himask = (shift == 24) ? 0u : (0xFFFFFFFFu << (shift + 8));
        #pragma unroll
        for (int c = 0; c < 4; c++)
            if ((u[c] & himask) == prefix)
                atomicAdd(&hist[(u[c] >> shift) & 255u], 1u);
        __syncthreads();
        if (tid < 32) {
            unsigned h[8], tot = 0;
            #pragma unroll
            for (int i = 0; i < 8; i++) { h[i] = hist[tid * 8 + i]; tot += h[i]; }
            unsigned s = tot;
            #pragma unroll
            for (int o = 1; o < 32; o <<= 1) {
                unsigned x = __shfl_down_sync(0xFFFFFFFFu, s, o);
                if (tid + o < 32) s += x;
            }
            unsigned run = s - tot;
            #pragma unroll
            for (int i = 7; i >= 0; i--) {
                unsigned greater = run;
                run += h[i];
                if (greater < k && k <= run) { s_bin = tid * 8 + i; s_k = k - greater; }
            }
        }
        __syncthreads();
        prefix |= s_bin << shift;
        k = s_k;
    }
    const unsigned thr_u = prefix;

    const float inv_t = 1.0f / 0.3f;
    float e[4];
    float lsum = 0.f;
    #pragma unroll
    for (int c = 0; c < 4; c++) {
        float adj = (u[c] >= thr_u) ? v[c] : -1e-7f;
        e[c] = __expf((adj - m) * inv_t);
        lsum += e[c];
    }
    #pragma unroll
    for (int o = 16; o > 0; o >>= 1)
        lsum += __shfl_xor_sync(0xFFFFFFFFu, lsum, o);
    if ((tid & 31) == 0) redf[tid >> 5] = lsum;
    __syncthreads();
    if (tid < 32) {
        float s = (tid < 8) ? redf[tid] : 0.f;
        #pragma unroll
        for (int o = 4; o > 0; o >>= 1)
            s += __shfl_xor_sync(0xFFFFFFFFu, s, o);
        if (tid == 0) redf[0] = s;
    }
    __syncthreads();
    const float inv_sum = 1.0f / redf[0];

    __nv_bfloat16 h[4], l[4];
    #pragma unroll
    for (int c = 0; c < 4; c++) {
        float p = e[c] * inv_sum;
        h[c] = bf_hi(p);
        l[c] = bf_lo(p, h[c]);
    }
    const long long i2 = (long long)blockIdx.x * (SEQ / 2) + tid * 2;
    ((__nv_bfloat162*)Ph)[i2]     = __halves2bfloat162(h[0], h[1]);
    ((__nv_bfloat162*)Ph)[i2 + 1] = __halves2bfloat162(h[2], h[3]);
    ((__nv_bfloat162*)Pl)[i2]     = __halves2bfloat162(l[0], l[1]);
    ((__nv_bfloat162*)Pl)[i2 + 1] = __halves2bfloat162(l[2], l[3]);
}

// ---------------- launch ----------------
extern "C" void kernel_launch(void* const* d_in, const int* in_sizes, int n_in,
                              void* d_out, int out_size)
{
    const float* h      = (const float*)d_in[0];
    const float* Wqk    = (const float*)d_in[1];
    const float* bqk    = (const float*)d_in[2];
    const float* weight = (const float*)d_in[3];
    const float* bias   = (const float*)d_in[4];
    float* out = (float*)d_out;

    __nv_bfloat16 *hh, *hl, *wqkTh, *wqkTl, *wTh, *wTl;
    __nv_bfloat16 *Qh, *Ql, *Kh, *Kl, *hWTh, *hWTl, *Ph, *Pl;
    float* at;
    cudaGetSymbolAddress((void**)&hh, g_hh);
    cudaGetSymbolAddress((void**)&hl, g_hl);
    cudaGetSymbolAddress((void**)&wqkTh, g_wqkTh);
    cudaGetSymbolAddress((void**)&wqkTl, g_wqkTl);
    cudaGetSymbolAddress((void**)&wTh, g_wTh);
    cudaGetSymbolAddress((void**)&wTl, g_wTl);
    cudaGetSymbolAddress((void**)&Qh, g_Qh);
    cudaGetSymbolAddress((void**)&Ql, g_Ql);
    cudaGetSymbolAddress((void**)&Kh, g_Kh);
    cudaGetSymbolAddress((void**)&Kl, g_Kl);
    cudaGetSymbolAddress((void**)&hWTh, g_hWTh);
    cudaGetSymbolAddress((void**)&hWTl, g_hWTl);
    cudaGetSymbolAddress((void**)&at, g_at);
    cudaGetSymbolAddress((void**)&Ph, g_Ph);
    cudaGetSymbolAddress((void**)&Pl, g_Pl);

    constexpr int SLDc = 40;
    const int SM128 = 2 * (2 * 128 * SLDc + 2 * 128 * SLDc) * 2;  // 81920 B
    const int SM64  = 2 * (2 * 128 * SLDc + 2 * 64 * SLDc) * 2;   // 61440 B
    cudaFuncSetAttribute(mm_gemm<128, 1>, cudaFuncAttributeMaxDynamicSharedMemorySize, SM128);
    cudaFuncSetAttribute(mm_gemm<128, 0>, cudaFuncAttributeMaxDynamicSharedMemorySize, SM128);
    cudaFuncSetAttribute(mm_gemm<64, 2>,  cudaFuncAttributeMaxDynamicSharedMemorySize, SM64);
    cudaFuncSetAttribute(mm_gemm<64, 3>,  cudaFuncAttributeMaxDynamicSharedMemorySize, SM64);

    const long long NF = (long long)SEQ * FDIM;
    const long long NN = (long long)SEQ * SEQ;

    // 0) splits
    split_kernel<<<(BATCH * SEQ * FDIM / 4 + 255) / 256, 256>>>(h, hh, hl,
                                                                BATCH * SEQ * FDIM / 4);
    transpose_split_kernel<<<dim3(PACK / 32, FDIM / 32), dim3(32, 8)>>>(
        Wqk, FDIM, PACK, wqkTh, wqkTl);
    transpose_split_kernel<<<dim3(FDIM / 32, FDIM / 32), dim3(32, 8)>>>(
        weight, FDIM, FDIM, wTh, wTl);

    // 1) proj: h @ Wqk (+bqk) fused even/odd split -> Q, K (K*0.125)
    mm_gemm<128, 1><<<dim3(PACK / 128, BATCH * SEQ / 128, 1), 256, SM128>>>(
        hh, hl, 0, FDIM, wqkTh, wqkTl, 0, FDIM,
        nullptr, 0, 0, bqk, Qh, Ql, Kh, Kl, FDIM);

    // 2) hW = h @ weight -> hWT splits [b][320][1024]
    mm_gemm<64, 2><<<dim3(FDIM / 64, BATCH * SEQ / 128, 1), 256, SM64>>>(
        hh, hl, 0, FDIM, wTh, wTl, 0, FDIM,
        nullptr, 0, 0, nullptr, hWTh, hWTl, nullptr, nullptr, FDIM);

    // 3) at[b] = Q[b] @ K[b]^T  (0.125 folded into K)
    mm_gemm<128, 0><<<dim3(SEQ / 128, SEQ / 128, BATCH), 256, SM128>>>(
        Qh, Ql, NF, FDIM, Kh, Kl, NF, FDIM,
        at, NN, SEQ, nullptr, nullptr, nullptr, nullptr, nullptr, FDIM);

    // 4) top-171 threshold + softmax -> attn bf16 splits
    mask_softmax_kernel<<<BATCH * SEQ, 256>>>(at, Ph, Pl);

    // 5) out[b] = attn[b] @ hW[b] + bias
    mm_gemm<64, 3><<<dim3(FDIM / 64, SEQ / 128, BATCH), 256, SM64>>>(
        Ph, Pl, NN, SEQ, hWTh, hWTl, NF, SEQ,
        out, 0, 0, bias, nullptr, nullptr, nullptr, nullptr, SEQ);
}

// round 6
// speedup vs baseline: 2.3057x; 1.0555x over previous
#include <cuda_runtime.h>
#include <cuda_bf16.h>

// B=8, N=1024, F=320, H=5, D=64, packed QK cols=640
// scale=0.125, TEMP=0.3, NEG_FILL=-1e-7, keep top N/6+1=171 per row

#define BATCH 8
#define SEQ   1024
#define FDIM  320
#define PACK  640
#define KSEL  171

// ---------------- scratch (device globals) ----------------
__device__ __align__(16) __nv_bfloat16 g_hh  [BATCH * SEQ * FDIM];
__device__ __align__(16) __nv_bfloat16 g_hl  [BATCH * SEQ * FDIM];
__device__ __align__(16) __nv_bfloat16 g_wqkTh[PACK * FDIM];
__device__ __align__(16) __nv_bfloat16 g_wqkTl[PACK * FDIM];
__device__ __align__(16) __nv_bfloat16 g_wTh [FDIM * FDIM];
__device__ __align__(16) __nv_bfloat16 g_wTl [FDIM * FDIM];
__device__ __align__(16) __nv_bfloat16 g_Qh  [BATCH * SEQ * FDIM];
__device__ __align__(16) __nv_bfloat16 g_Ql  [BATCH * SEQ * FDIM];
__device__ __align__(16) __nv_bfloat16 g_Kh  [BATCH * SEQ * FDIM];
__device__ __align__(16) __nv_bfloat16 g_Kl  [BATCH * SEQ * FDIM];
__device__ __align__(16) __nv_bfloat16 g_hWTh[BATCH * FDIM * SEQ];
__device__ __align__(16) __nv_bfloat16 g_hWTl[BATCH * FDIM * SEQ];
__device__ __align__(16) float         g_at  [BATCH * SEQ * SEQ];
__device__ __align__(16) __nv_bfloat16 g_Ph  [BATCH * SEQ * SEQ];
__device__ __align__(16) __nv_bfloat16 g_Pl  [BATCH * SEQ * SEQ];

// ---------------- helpers ----------------
__device__ __forceinline__ void cpa16(unsigned s, const void* g) {
    asm volatile("cp.async.cg.shared.global [%0], [%1], 16;" :: "r"(s), "l"(g));
}
__device__ __forceinline__ unsigned smem_u32(const void* p) {
    unsigned a;
    asm("{ .reg .u64 t; cvta.to.shared.u64 t, %1; cvt.u32.u64 %0, t; }"
        : "=r"(a) : "l"(p));
    return a;
}
__device__ __forceinline__ __nv_bfloat16 bf_hi(float v) { return __float2bfloat16_rn(v); }
__device__ __forceinline__ __nv_bfloat16 bf_lo(float v, __nv_bfloat16 h) {
    return __float2bfloat16_rn(v - __bfloat162float(h));
}
__device__ __forceinline__ void mma16816(float* d, const unsigned* a, const unsigned* b) {
    asm volatile(
        "mma.sync.aligned.m16n8k16.row.col.f32.bf16.bf16.f32 "
        "{%0,%1,%2,%3}, {%4,%5,%6,%7}, {%8,%9}, {%0,%1,%2,%3};"
        : "+f"(d[0]), "+f"(d[1]), "+f"(d[2]), "+f"(d[3])
        : "r"(a[0]), "r"(a[1]), "r"(a[2]), "r"(a[3]), "r"(b[0]), "r"(b[1]));
}

#define SLD 40   // smem pitch (bf16): 80B rows -> conflict-free fragment LDS

__device__ __forceinline__ void ldA(unsigned a[4], const __nv_bfloat16* As,
                                    int row0, int kk, int g, int t) {
    const __nv_bfloat16* p = As + (row0 + g) * SLD + kk + 2 * t;
    a[0] = *(const unsigned*)p;
    a[1] = *(const unsigned*)(p + 8 * SLD);
    a[2] = *(const unsigned*)(p + 8);
    a[3] = *(const unsigned*)(p + 8 * SLD + 8);
}
__device__ __forceinline__ void ldB(unsigned b[2], const __nv_bfloat16* Bs,
                                    int n0, int kk, int g, int t) {
    const __nv_bfloat16* p = Bs + (n0 + g) * SLD + kk + 2 * t;
    b[0] = *(const unsigned*)p;
    b[1] = *(const unsigned*)(p + 8);
}

// ---------------- mma.sync split-bf16 GEMM (128x64 tile, 2 CTAs/SM) ---------
// C[m,n] = sum_k A[m,k] * B[n,k]; A,B bf16 (hi,lo) K-major; fp32 acc.
// 3-term compensation: hi*hi + hi*lo + lo*hi.
// EPI: 0 fp32 C; 1 proj -> Q/K hi/lo (+bqk, K*0.125); 2 hWT hi/lo; 3 fp32 out+bias.
template<int EPI>
__global__ __launch_bounds__(256, 2) void mm_gemm(
    const __nv_bfloat16* __restrict__ Ah, const __nv_bfloat16* __restrict__ Al,
    long long sA, int lda,
    const __nv_bfloat16* __restrict__ Bh, const __nv_bfloat16* __restrict__ Bl,
    long long sB, int ldb,
    float* __restrict__ Cout, long long sC, int ldc,
    const float* __restrict__ bias,
    __nv_bfloat16* __restrict__ O1h, __nv_bfloat16* __restrict__ O1l,
    __nv_bfloat16* __restrict__ O2h, __nv_bfloat16* __restrict__ O2l,
    int Ktot)
{
    constexpr int BN = 64;
    constexpr int WX = 2, WM = 32, WN = 32;
    constexpr int MT = WM / 16;            // 2
    constexpr int NT = WN / 8;             // 4
    constexpr int ASZ = 128 * SLD;         // bf16 elements
    constexpr int BSZ = BN * SLD;
    constexpr int STAGE = 2 * ASZ + 2 * BSZ;

    extern __shared__ __nv_bfloat16 smem[];

    const int tid = threadIdx.x;
    const int wid = tid >> 5;
    const int lane = tid & 31;
    const int g = lane >> 2, t = lane & 3;
    const int wy = wid / WX, wx = wid % WX;

    const __nv_bfloat16* Ath = Ah + blockIdx.z * sA + (long long)blockIdx.y * 128 * lda;
    const __nv_bfloat16* Atl = Al + blockIdx.z * sA + (long long)blockIdx.y * 128 * lda;
    const __nv_bfloat16* Bth = Bh + blockIdx.z * sB + (long long)blockIdx.x * BN * ldb;
    const __nv_bfloat16* Btl = Bl + blockIdx.z * sB + (long long)blockIdx.x * BN * ldb;

    const unsigned sb0 = smem_u32(smem);
    const int S = Ktot >> 5;

    auto load_stage = [&](int s) {
        const unsigned sb = sb0 + (s & 1) * STAGE * 2;   // bytes
        const int k0 = s << 5;
        #pragma unroll
        for (int q = tid; q < 512; q += 256) {
            int row = q >> 2, c = q & 3;
            unsigned so = sb + (row * SLD + c * 8) * 2;
            cpa16(so,           Ath + (long long)row * lda + k0 + c * 8);
            cpa16(so + ASZ * 2, Atl + (long long)row * lda + k0 + c * 8);
        }
        {
            int row = tid >> 2, c = tid & 3;
            unsigned so = sb + 4 * ASZ + (row * SLD + c * 8) * 2;
            cpa16(so,           Bth + (long long)row * ldb + k0 + c * 8);
            cpa16(so + BSZ * 2, Btl + (long long)row * ldb + k0 + c * 8);
        }
        asm volatile("cp.async.commit_group;" ::: "memory");
    };

    float acc[MT][NT][4];
    #pragma unroll
    for (int i = 0; i < MT; i++)
        #pragma unroll
        for (int j = 0; j < NT; j++)
            #pragma unroll
            for (int r = 0; r < 4; r++) acc[i][j][r] = 0.f;

    load_stage(0);
    for (int s = 0; s < S; s++) {
        if (s + 1 < S) {
            load_stage(s + 1);
            asm volatile("cp.async.wait_group 1;" ::: "memory");
        } else {
            asm volatile("cp.async.wait_group 0;" ::: "memory");
        }
        __syncthreads();

        const __nv_bfloat16* Ahs = smem + (s & 1) * STAGE;
        const __nv_bfloat16* Als = Ahs + ASZ;
        const __nv_bfloat16* Bhs = Ahs + 2 * ASZ;
        const __nv_bfloat16* Bls = Ahs + 2 * ASZ + BSZ;

        #pragma unroll
        for (int kk = 0; kk < 32; kk += 16) {
            unsigned ah[MT][4], al[MT][4], bh[NT][2], bl[NT][2];
            #pragma unroll
            for (int mt = 0; mt < MT; mt++) {
                ldA(ah[mt], Ahs, wy * WM + mt * 16, kk, g, t);
                ldA(al[mt], Als, wy * WM + mt * 16, kk, g, t);
            }
            #pragma unroll
            for (int nt = 0; nt < NT; nt++) {
                ldB(bh[nt], Bhs, wx * WN + nt * 8, kk, g, t);
                ldB(bl[nt], Bls, wx * WN + nt * 8, kk, g, t);
            }
            #pragma unroll
            for (int mt = 0; mt < MT; mt++)
                #pragma unroll
                for (int nt = 0; nt < NT; nt++) {
                    mma16816(acc[mt][nt], ah[mt], bh[nt]);
                    mma16816(acc[mt][nt], ah[mt], bl[nt]);
                    mma16816(acc[mt][nt], al[mt], bh[nt]);
                }
        }
        __syncthreads();
    }

    // ---------------- epilogue ----------------
    #pragma unroll
    for (int mt = 0; mt < MT; mt++) {
        #pragma unroll
        for (int nt = 0; nt < NT; nt++) {
            const float* c = acc[mt][nt];
            const int mloc = wy * WM + mt * 16 + g;
            const int nloc = wx * WN + nt * 8 + 2 * t;
            const long long mg = (long long)blockIdx.y * 128 + mloc;
            const int ng = blockIdx.x * BN + nloc;

            if constexpr (EPI == 0) {
                float* C0 = Cout + blockIdx.z * sC + mg * ldc + ng;
                *(float2*)C0               = make_float2(c[0], c[1]);
                *(float2*)(C0 + 8LL * ldc) = make_float2(c[2], c[3]);
            } else if constexpr (EPI == 1) {
                const float b0 = bias[ng], b1 = bias[ng + 1];
                const int f = ng >> 1;
                float q0 = c[0] + b0, k0 = (c[1] + b1) * 0.125f;
                float q1 = c[2] + b0, k1 = (c[3] + b1) * 0.125f;
                long long u0 = mg * FDIM + f;
                long long u1 = (mg + 8) * FDIM + f;
                __nv_bfloat16 h;
                h = bf_hi(q0); O1h[u0] = h; O1l[u0] = bf_lo(q0, h);
                h = bf_hi(k0); O2h[u0] = h; O2l[u0] = bf_lo(k0, h);
                h = bf_hi(q1); O1h[u1] = h; O1l[u1] = bf_lo(q1, h);
                h = bf_hi(k1); O2h[u1] = h; O2l[u1] = bf_lo(k1, h);
            } else if constexpr (EPI == 2) {
                const int b = (int)(mg >> 10);
                const int ml = (int)(mg & 1023);
                long long o = ((long long)b * FDIM + ng) * SEQ + ml;
                __nv_bfloat16 h;
                h = bf_hi(c[0]); O1h[o] = h;            O1l[o] = bf_lo(c[0], h);
                h = bf_hi(c[1]); O1h[o + SEQ] = h;      O1l[o + SEQ] = bf_lo(c[1], h);
                h = bf_hi(c[2]); O1h[o + 8] = h;        O1l[o + 8] = bf_lo(c[2], h);
                h = bf_hi(c[3]); O1h[o + SEQ + 8] = h;  O1l[o + SEQ + 8] = bf_lo(c[3], h);
            } else {
                const float b0 = bias[ng], b1 = bias[ng + 1];
                float* C0 = Cout + (blockIdx.z * (long long)SEQ + mg) * FDIM + ng;
                *(float2*)C0                = make_float2(c[0] + b0, c[1] + b1);
                *(float2*)(C0 + 8LL * FDIM) = make_float2(c[2] + b0, c[3] + b1);
            }
        }
    }
}

// ---------------- prep: fp32 -> bf16 hi/lo split ----------------
__global__ void split_kernel(const float* __restrict__ src,
                             __nv_bfloat16* __restrict__ hi,
                             __nv_bfloat16* __restrict__ lo, int n4)
{
    int i = blockIdx.x * blockDim.x + threadIdx.x;
    if (i < n4) {
        float4 v = ((const float4*)src)[i];
        float a[4] = {v.x, v.y, v.z, v.w};
        __nv_bfloat16 h[4], l[4];
        #pragma unroll
        for (int c = 0; c < 4; c++) { h[c] = bf_hi(a[c]); l[c] = bf_lo(a[c], h[c]); }
        ((__nv_bfloat162*)hi)[2 * i]     = __halves2bfloat162(h[0], h[1]);
        ((__nv_bfloat162*)hi)[2 * i + 1] = __halves2bfloat162(h[2], h[3]);
        ((__nv_bfloat162*)lo)[2 * i]     = __halves2bfloat162(l[0], l[1]);
        ((__nv_bfloat162*)lo)[2 * i + 1] = __halves2bfloat162(l[2], l[3]);
    }
}

// ---------------- prep: transpose + split ----------------
__global__ void transpose_split_kernel(const float* __restrict__ src, int R, int C,
                                       __nv_bfloat16* __restrict__ th,
                                       __nv_bfloat16* __restrict__ tl)
{
    __shared__ float tbuf[32][33];
    int x = blockIdx.x * 32 + threadIdx.x;
    int y0 = blockIdx.y * 32;
    #pragma unroll
    for (int j = threadIdx.y; j < 32; j += 8)
        tbuf[j][threadIdx.x] = src[(long long)(y0 + j) * C + x];
    __syncthreads();
    int xo = y0 + threadIdx.x;
    int co = blockIdx.x * 32;
    #pragma unroll
    for (int j = threadIdx.y; j < 32; j += 8) {
        float v = tbuf[threadIdx.x][j];
        __nv_bfloat16 h = bf_hi(v);
        th[(long long)(co + j) * R + xo] = h;
        tl[(long long)(co + j) * R + xo] = bf_lo(v, h);
    }
}

// ---------------- radix-select top-k + masked softmax -> bf16 splits --------
__global__ __launch_bounds__(256) void mask_softmax_kernel(
    const float* __restrict__ at,
    __nv_bfloat16* __restrict__ Ph, __nv_bfloat16* __restrict__ Pl)
{
    __shared__ unsigned hist[256];
    __shared__ float redf[8];
    __shared__ unsigned s_bin, s_k;

    const int tid = threadIdx.x;
    const float* row = at + (long long)blockIdx.x * SEQ;

    float4 vv = *(const float4*)(row + tid * 4);
    float v[4] = {vv.x, vv.y, vv.z, vv.w};
    unsigned u[4];
    float lmax = -3.402823466e38f;
    #pragma unroll
    for (int c = 0; c < 4; c++) {
        unsigned b = __float_as_uint(v[c]);
        u[c] = (b & 0x80000000u) ? ~b : (b | 0x80000000u);
        lmax = fmaxf(lmax, v[c]);
    }
    #pragma unroll
    for (int o = 16; o > 0; o >>= 1)
        lmax = fmaxf(lmax, __shfl_xor_sync(0xFFFFFFFFu, lmax, o));
    if ((tid & 31) == 0) redf[tid >> 5] = lmax;
    __syncthreads();
    if (tid < 32) {
        float m = (tid < 8) ? redf[tid] : -3.402823466e38f;
        #pragma unroll
        for (int o = 4; o > 0; o >>= 1)
            m = fmaxf(m, __shfl_xor_sync(0xFFFFFFFFu, m, o));
        if (tid == 0) redf[0] = m;
    }
    __syncthreads();
    const float m = redf[0];

    unsigned prefix = 0, k = KSEL;
    #pragma unroll
    for (int shift = 24; shift >= 0; shift -= 8) {
        hist[tid] = 0;
        __syncthreads();
        const unsigned himask = (shift == 24) ? 0u : (0xFFFFFFFFu << (shift + 8));
        #pragma unroll
        for (int c = 0; c < 4; c++)
            if ((u[c] & himask) == prefix)
                atomicAdd(&hist[(u[c] >> shift) & 255u], 1u);
        __syncthreads();
        if (tid < 32) {
            unsigned h[8], tot = 0;
            #pragma unroll
            for (int i = 0; i < 8; i++) { h[i] = hist[tid * 8 + i]; tot += h[i]; }
            unsigned s = tot;
            #pragma unroll
            for (int o = 1; o < 32; o <<= 1) {
                unsigned x = __shfl_down_sync(0xFFFFFFFFu, s, o);
                if (tid + o < 32) s += x;
            }
            unsigned run = s - tot;
            #pragma unroll
            for (int i = 7; i >= 0; i--) {
                unsigned greater = run;
                run += h[i];
                if (greater < k && k <= run) { s_bin = tid * 8 + i; s_k = k - greater; }
            }
        }
        __syncthreads();
        prefix |= s_bin << shift;
        k = s_k;
    }
    const unsigned thr_u = prefix;

    const float inv_t = 1.0f / 0.3f;
    float e[4];
    float lsum = 0.f;
    #pragma unroll
    for (int c = 0; c < 4; c++) {
        float adj = (u[c] >= thr_u) ? v[c] : -1e-7f;
        e[c] = __expf((adj - m) * inv_t);
        lsum += e[c];
    }
    #pragma unroll
    for (int o = 16; o > 0; o >>= 1)
        lsum += __shfl_xor_sync(0xFFFFFFFFu, lsum, o);
    if ((tid & 31) == 0) redf[tid >> 5] = lsum;
    __syncthreads();
    if (tid < 32) {
        float s = (tid < 8) ? redf[tid] : 0.f;
        #pragma unroll
        for (int o = 4; o > 0; o >>= 1)
            s += __shfl_xor_sync(0xFFFFFFFFu, s, o);
        if (tid == 0) redf[0] = s;
    }
    __syncthreads();
    const float inv_sum = 1.0f / redf[0];

    __nv_bfloat16 h[4], l[4];
    #pragma unroll
    for (int c = 0; c < 4; c++) {
        float p = e[c] * inv_sum;
        h[c] = bf_hi(p);
        l[c] = bf_lo(p, h[c]);
    }
    const long long i2 = (long long)blockIdx.x * (SEQ / 2) + tid * 2;
    ((__nv_bfloat162*)Ph)[i2]     = __halves2bfloat162(h[0], h[1]);
    ((__nv_bfloat162*)Ph)[i2 + 1] = __halves2bfloat162(h[2], h[3]);
    ((__nv_bfloat162*)Pl)[i2]     = __halves2bfloat162(l[0], l[1]);
    ((__nv_bfloat162*)Pl)[i2 + 1] = __halves2bfloat162(l[2], l[3]);
}

// ---------------- launch ----------------
extern "C" void kernel_launch(void* const* d_in, const int* in_sizes, int n_in,
                              void* d_out, int out_size)
{
    const float* h      = (const float*)d_in[0];
    const float* Wqk    = (const float*)d_in[1];
    const float* bqk    = (const float*)d_in[2];
    const float* weight = (const float*)d_in[3];
    const float* bias   = (const float*)d_in[4];
    float* out = (float*)d_out;

    __nv_bfloat16 *hh, *hl, *wqkTh, *wqkTl, *wTh, *wTl;
    __nv_bfloat16 *Qh, *Ql, *Kh, *Kl, *hWTh, *hWTl, *Ph, *Pl;
    float* at;
    cudaGetSymbolAddress((void**)&hh, g_hh);
    cudaGetSymbolAddress((void**)&hl, g_hl);
    cudaGetSymbolAddress((void**)&wqkTh, g_wqkTh);
    cudaGetSymbolAddress((void**)&wqkTl, g_wqkTl);
    cudaGetSymbolAddress((void**)&wTh, g_wTh);
    cudaGetSymbolAddress((void**)&wTl, g_wTl);
    cudaGetSymbolAddress((void**)&Qh, g_Qh);
    cudaGetSymbolAddress((void**)&Ql, g_Ql);
    cudaGetSymbolAddress((void**)&Kh, g_Kh);
    cudaGetSymbolAddress((void**)&Kl, g_Kl);
    cudaGetSymbolAddress((void**)&hWTh, g_hWTh);
    cudaGetSymbolAddress((void**)&hWTl, g_hWTl);
    cudaGetSymbolAddress((void**)&at, g_at);
    cudaGetSymbolAddress((void**)&Ph, g_Ph);
    cudaGetSymbolAddress((void**)&Pl, g_Pl);

    // stage = (2*128*40 + 2*64*40) * 2B = 30720B; double-buffered = 61440B
    const int SMB = 61440;
    cudaFuncSetAttribute(mm_gemm<0>, cudaFuncAttributeMaxDynamicSharedMemorySize, SMB);
    cudaFuncSetAttribute(mm_gemm<1>, cudaFuncAttributeMaxDynamicSharedMemorySize, SMB);
    cudaFuncSetAttribute(mm_gemm<2>, cudaFuncAttributeMaxDynamicSharedMemorySize, SMB);
    cudaFuncSetAttribute(mm_gemm<3>, cudaFuncAttributeMaxDynamicSharedMemorySize, SMB);

    const long long NF = (long long)SEQ * FDIM;
    const long long NN = (long long)SEQ * SEQ;

    // 0) splits
    split_kernel<<<(BATCH * SEQ * FDIM / 4 + 255) / 256, 256>>>(h, hh, hl,
                                                                BATCH * SEQ * FDIM / 4);
    transpose_split_kernel<<<dim3(PACK / 32, FDIM / 32), dim3(32, 8)>>>(
        Wqk, FDIM, PACK, wqkTh, wqkTl);
    transpose_split_kernel<<<dim3(FDIM / 32, FDIM / 32), dim3(32, 8)>>>(
        weight, FDIM, FDIM, wTh, wTl);

    // 1) proj: h @ Wqk (+bqk) fused even/odd split -> Q, K (K*0.125)
    mm_gemm<1><<<dim3(PACK / 64, BATCH * SEQ / 128, 1), 256, SMB>>>(
        hh, hl, 0, FDIM, wqkTh, wqkTl, 0, FDIM,
        nullptr, 0, 0, bqk, Qh, Ql, Kh, Kl, FDIM);

    // 2) hW = h @ weight -> hWT splits [b][320][1024]
    mm_gemm<2><<<dim3(FDIM / 64, BATCH * SEQ / 128, 1), 256, SMB>>>(
        hh, hl, 0, FDIM, wTh, wTl, 0, FDIM,
        nullptr, 0, 0, nullptr, hWTh, hWTl, nullptr, nullptr, FDIM);

    // 3) at[b] = Q[b] @ K[b]^T  (0.125 folded into K)
    mm_gemm<0><<<dim3(SEQ / 64, SEQ / 128, BATCH), 256, SMB>>>(
        Qh, Ql, NF, FDIM, Kh, Kl, NF, FDIM,
        at, NN, SEQ, nullptr, nullptr, nullptr, nullptr, nullptr, FDIM);

    // 4) top-171 threshold + softmax -> attn bf16 splits
    mask_softmax_kernel<<<BATCH * SEQ, 256>>>(at, Ph, Pl);

    // 5) out[b] = attn[b] @ hW[b] + bias
    mm_gemm<3><<<dim3(FDIM / 64, SEQ / 128, BATCH), 256, SMB>>>(
        Ph, Pl, NN, SEQ, hWTh, hWTl, NF, SEQ,
        out, 0, 0, bias, nullptr, nullptr, nullptr, nullptr, SEQ);
}

// round 7
// speedup vs baseline: 2.4302x; 1.0540x over previous
#include <cuda_runtime.h>
#include <cuda_bf16.h>

// B=8, N=1024, F=320, H=5, D=64, packed QK cols=640
// scale=0.125, TEMP=0.3, NEG_FILL=-1e-7, keep top N/6+1=171 per row

#define BATCH 8
#define SEQ   1024
#define FDIM  320
#define PACK  640
#define KSEL  171

// ---------------- scratch (device globals) ----------------
__device__ __align__(16) __nv_bfloat16 g_hh  [BATCH * SEQ * FDIM];
__device__ __align__(16) __nv_bfloat16 g_hl  [BATCH * SEQ * FDIM];
__device__ __align__(16) __nv_bfloat16 g_wqkTh[PACK * FDIM];
__device__ __align__(16) __nv_bfloat16 g_wqkTl[PACK * FDIM];
__device__ __align__(16) __nv_bfloat16 g_wTh [FDIM * FDIM];
__device__ __align__(16) __nv_bfloat16 g_wTl [FDIM * FDIM];
__device__ __align__(16) __nv_bfloat16 g_Qh  [BATCH * SEQ * FDIM];
__device__ __align__(16) __nv_bfloat16 g_Ql  [BATCH * SEQ * FDIM];
__device__ __align__(16) __nv_bfloat16 g_Kh  [BATCH * SEQ * FDIM];
__device__ __align__(16) __nv_bfloat16 g_Kl  [BATCH * SEQ * FDIM];
__device__ __align__(16) __nv_bfloat16 g_hWTh[BATCH * FDIM * SEQ];
__device__ __align__(16) __nv_bfloat16 g_hWTl[BATCH * FDIM * SEQ];
__device__ __align__(16) float         g_at  [BATCH * SEQ * SEQ];
__device__ __align__(16) __nv_bfloat16 g_Ph  [BATCH * SEQ * SEQ];
__device__ __align__(16) __nv_bfloat16 g_Pl  [BATCH * SEQ * SEQ];

// ---------------- helpers ----------------
__device__ __forceinline__ void cpa16(unsigned s, const void* g) {
    asm volatile("cp.async.cg.shared.global [%0], [%1], 16;" :: "r"(s), "l"(g));
}
__device__ __forceinline__ unsigned smem_u32(const void* p) {
    unsigned a;
    asm("{ .reg .u64 t; cvta.to.shared.u64 t, %1; cvt.u32.u64 %0, t; }"
        : "=r"(a) : "l"(p));
    return a;
}
__device__ __forceinline__ __nv_bfloat16 bf_hi(float v) { return __float2bfloat16_rn(v); }
__device__ __forceinline__ __nv_bfloat16 bf_lo(float v, __nv_bfloat16 h) {
    return __float2bfloat16_rn(v - __bfloat162float(h));
}
__device__ __forceinline__ void mma16816(float* d, const unsigned* a, const unsigned* b) {
    asm volatile(
        "mma.sync.aligned.m16n8k16.row.col.f32.bf16.bf16.f32 "
        "{%0,%1,%2,%3}, {%4,%5,%6,%7}, {%8,%9}, {%0,%1,%2,%3};"
        : "+f"(d[0]), "+f"(d[1]), "+f"(d[2]), "+f"(d[3])
        : "r"(a[0]), "r"(a[1]), "r"(a[2]), "r"(a[3]), "r"(b[0]), "r"(b[1]));
}
__device__ __forceinline__ void ldsm4(unsigned* r, unsigned addr) {
    asm volatile("ldmatrix.sync.aligned.m8n8.x4.shared.b16 {%0,%1,%2,%3}, [%4];"
                 : "=r"(r[0]), "=r"(r[1]), "=r"(r[2]), "=r"(r[3]) : "r"(addr));
}

#define SLD 40   // smem pitch (bf16): 80B rows -> ldmatrix phases conflict-free

// ---------------- mma.sync split-bf16 GEMM (128x64 tile, ldmatrix, 3-stage) -
// C[m,n] = sum_k A[m,k] * B[n,k]; A,B bf16 (hi,lo) K-major; fp32 acc.
// 3-term compensation: hi*hi + hi*lo + lo*hi.
// EPI: 0 fp32 C; 1 proj -> Q/K hi/lo (+bqk, K*0.125); 2 hWT hi/lo; 3 fp32 out+bias.
template<int EPI>
__global__ __launch_bounds__(256, 2) void mm_gemm(
    const __nv_bfloat16* __restrict__ Ah, const __nv_bfloat16* __restrict__ Al,
    long long sA, int lda,
    const __nv_bfloat16* __restrict__ Bh, const __nv_bfloat16* __restrict__ Bl,
    long long sB, int ldb,
    float* __restrict__ Cout, long long sC, int ldc,
    const float* __restrict__ bias,
    __nv_bfloat16* __restrict__ O1h, __nv_bfloat16* __restrict__ O1l,
    __nv_bfloat16* __restrict__ O2h, __nv_bfloat16* __restrict__ O2l,
    int Ktot)
{
    constexpr int BN = 64;
    constexpr int WX = 2, WM = 32, WN = 32;
    constexpr int MT = 2, NT = 4;
    constexpr int ASZ = 128 * SLD;              // bf16 elements per A matrix
    constexpr int BSZ = BN * SLD;
    constexpr int STG = (2 * ASZ + 2 * BSZ) * 2;  // stage bytes = 30720
    constexpr int OFF_AL = ASZ * 2;
    constexpr int OFF_BH = 4 * ASZ;
    constexpr int OFF_BL = 4 * ASZ + BSZ * 2;

    extern __shared__ __nv_bfloat16 smem[];

    const int tid = threadIdx.x;
    const int wid = tid >> 5;
    const int lane = tid & 31;
    const int g = lane >> 2, t = lane & 3;
    const int wy = wid / WX, wx = wid % WX;

    const __nv_bfloat16* Ath = Ah + blockIdx.z * sA + (long long)blockIdx.y * 128 * lda;
    const __nv_bfloat16* Atl = Al + blockIdx.z * sA + (long long)blockIdx.y * 128 * lda;
    const __nv_bfloat16* Bth = Bh + blockIdx.z * sB + (long long)blockIdx.x * BN * ldb;
    const __nv_bfloat16* Btl = Bl + blockIdx.z * sB + (long long)blockIdx.x * BN * ldb;

    const unsigned sb0 = smem_u32(smem);
    const int S = Ktot >> 5;

    // per-lane ldmatrix base offsets (bytes, within a stage)
    unsigned aoff[MT], boff[2];
    {
        int ar = (lane & 7) + ((lane >> 3) & 1) * 8;   // row within 16
        int ac = (lane >> 4) * 8;                      // 0 or 8 (k)
        #pragma unroll
        for (int mt = 0; mt < MT; mt++)
            aoff[mt] = ((wy * WM + mt * 16 + ar) * SLD + ac) * 2;
        int br = (lane & 7) + ((lane >> 4) & 1) * 8;   // row within pair-of-8
        int bc = ((lane >> 3) & 1) * 8;
        #pragma unroll
        for (int p = 0; p < 2; p++)
            boff[p] = ((wx * WN + p * 16 + br) * SLD + bc) * 2;
    }

    auto load_stage = [&](int s) {
        const unsigned sb = sb0 + (s % 3) * STG;
        const int k0 = s << 5;
        #pragma unroll
        for (int q = tid; q < 512; q += 256) {
            int row = q >> 2, c = q & 3;
            unsigned so = sb + (row * SLD + c * 8) * 2;
            cpa16(so,          Ath + (long long)row * lda + k0 + c * 8);
            cpa16(so + OFF_AL, Atl + (long long)row * lda + k0 + c * 8);
        }
        {
            int row = tid >> 2, c = tid & 3;
            unsigned so = sb + OFF_BH + (row * SLD + c * 8) * 2;
            cpa16(so,                    Bth + (long long)row * ldb + k0 + c * 8);
            cpa16(so + (OFF_BL - OFF_BH), Btl + (long long)row * ldb + k0 + c * 8);
        }
        asm volatile("cp.async.commit_group;" ::: "memory");
    };

    float acc[MT][NT][4];
    #pragma unroll
    for (int i = 0; i < MT; i++)
        #pragma unroll
        for (int j = 0; j < NT; j++)
            #pragma unroll
            for (int r = 0; r < 4; r++) acc[i][j][r] = 0.f;

    load_stage(0);
    if (S > 1) load_stage(1);

    for (int s = 0; s < S; s++) {
        if (s == S - 1) asm volatile("cp.async.wait_group 0;" ::: "memory");
        else            asm volatile("cp.async.wait_group 1;" ::: "memory");
        __syncthreads();
        if (s + 2 < S) load_stage(s + 2);

        const unsigned sb = sb0 + (s % 3) * STG;

        #pragma unroll
        for (int kk = 0; kk < 32; kk += 16) {
            unsigned ah[MT][4], al[MT][4], bh[2][4], bl[2][4];
            #pragma unroll
            for (int mt = 0; mt < MT; mt++) {
                ldsm4(ah[mt], sb + aoff[mt] + kk * 2);
                ldsm4(al[mt], sb + OFF_AL + aoff[mt] + kk * 2);
            }
            #pragma unroll
            for (int p = 0; p < 2; p++) {
                ldsm4(bh[p], sb + OFF_BH + boff[p] + kk * 2);
                ldsm4(bl[p], sb + OFF_BL + boff[p] + kk * 2);
            }
            #pragma unroll
            for (int mt = 0; mt < MT; mt++)
                #pragma unroll
                for (int nt = 0; nt < NT; nt++) {
                    const unsigned* bhf = &bh[nt >> 1][(nt & 1) * 2];
                    const unsigned* blf = &bl[nt >> 1][(nt & 1) * 2];
                    mma16816(acc[mt][nt], ah[mt], bhf);
                    mma16816(acc[mt][nt], ah[mt], blf);
                    mma16816(acc[mt][nt], al[mt], bhf);
                }
        }
        __syncthreads();
    }

    // ---------------- epilogue ----------------
    #pragma unroll
    for (int mt = 0; mt < MT; mt++) {
        #pragma unroll
        for (int nt = 0; nt < NT; nt++) {
            const float* c = acc[mt][nt];
            const int mloc = wy * WM + mt * 16 + g;
            const int nloc = wx * WN + nt * 8 + 2 * t;
            const long long mg = (long long)blockIdx.y * 128 + mloc;
            const int ng = blockIdx.x * BN + nloc;

            if constexpr (EPI == 0) {
                float* C0 = Cout + blockIdx.z * sC + mg * ldc + ng;
                *(float2*)C0               = make_float2(c[0], c[1]);
                *(float2*)(C0 + 8LL * ldc) = make_float2(c[2], c[3]);
            } else if constexpr (EPI == 1) {
                const float b0 = bias[ng], b1 = bias[ng + 1];
                const int f = ng >> 1;
                float q0 = c[0] + b0, k0 = (c[1] + b1) * 0.125f;
                float q1 = c[2] + b0, k1 = (c[3] + b1) * 0.125f;
                long long u0 = mg * FDIM + f;
                long long u1 = (mg + 8) * FDIM + f;
                __nv_bfloat16 h;
                h = bf_hi(q0); O1h[u0] = h; O1l[u0] = bf_lo(q0, h);
                h = bf_hi(k0); O2h[u0] = h; O2l[u0] = bf_lo(k0, h);
                h = bf_hi(q1); O1h[u1] = h; O1l[u1] = bf_lo(q1, h);
                h = bf_hi(k1); O2h[u1] = h; O2l[u1] = bf_lo(k1, h);
            } else if constexpr (EPI == 2) {
                const int b = (int)(mg >> 10);
                const int ml = (int)(mg & 1023);
                long long o = ((long long)b * FDIM + ng) * SEQ + ml;
                __nv_bfloat16 h;
                h = bf_hi(c[0]); O1h[o] = h;            O1l[o] = bf_lo(c[0], h);
                h = bf_hi(c[1]); O1h[o + SEQ] = h;      O1l[o + SEQ] = bf_lo(c[1], h);
                h = bf_hi(c[2]); O1h[o + 8] = h;        O1l[o + 8] = bf_lo(c[2], h);
                h = bf_hi(c[3]); O1h[o + SEQ + 8] = h;  O1l[o + SEQ + 8] = bf_lo(c[3], h);
            } else {
                const float b0 = bias[ng], b1 = bias[ng + 1];
                float* C0 = Cout + (blockIdx.z * (long long)SEQ + mg) * FDIM + ng;
                *(float2*)C0                = make_float2(c[0] + b0, c[1] + b1);
                *(float2*)(C0 + 8LL * FDIM) = make_float2(c[2] + b0, c[3] + b1);
            }
        }
    }
}

// ---------------- prep: fp32 -> bf16 hi/lo split ----------------
__global__ void split_kernel(const float* __restrict__ src,
                             __nv_bfloat16* __restrict__ hi,
                             __nv_bfloat16* __restrict__ lo, int n4)
{
    int i = blockIdx.x * blockDim.x + threadIdx.x;
    if (i < n4) {
        float4 v = ((const float4*)src)[i];
        float a[4] = {v.x, v.y, v.z, v.w};
        __nv_bfloat16 h[4], l[4];
        #pragma unroll
        for (int c = 0; c < 4; c++) { h[c] = bf_hi(a[c]); l[c] = bf_lo(a[c], h[c]); }
        ((__nv_bfloat162*)hi)[2 * i]     = __halves2bfloat162(h[0], h[1]);
        ((__nv_bfloat162*)hi)[2 * i + 1] = __halves2bfloat162(h[2], h[3]);
        ((__nv_bfloat162*)lo)[2 * i]     = __halves2bfloat162(l[0], l[1]);
        ((__nv_bfloat162*)lo)[2 * i + 1] = __halves2bfloat162(l[2], l[3]);
    }
}

// ---------------- prep: transpose + split ----------------
__global__ void transpose_split_kernel(const float* __restrict__ src, int R, int C,
                                       __nv_bfloat16* __restrict__ th,
                                       __nv_bfloat16* __restrict__ tl)
{
    __shared__ float tbuf[32][33];
    int x = blockIdx.x * 32 + threadIdx.x;
    int y0 = blockIdx.y * 32;
    #pragma unroll
    for (int j = threadIdx.y; j < 32; j += 8)
        tbuf[j][threadIdx.x] = src[(long long)(y0 + j) * C + x];
    __syncthreads();
    int xo = y0 + threadIdx.x;
    int co = blockIdx.x * 32;
    #pragma unroll
    for (int j = threadIdx.y; j < 32; j += 8) {
        float v = tbuf[threadIdx.x][j];
        __nv_bfloat16 h = bf_hi(v);
        th[(long long)(co + j) * R + xo] = h;
        tl[(long long)(co + j) * R + xo] = bf_lo(v, h);
    }
}

// ---------------- radix-select top-k + masked softmax -> bf16 splits --------
__global__ __launch_bounds__(256) void mask_softmax_kernel(
    const float* __restrict__ at,
    __nv_bfloat16* __restrict__ Ph, __nv_bfloat16* __restrict__ Pl)
{
    __shared__ unsigned hist[256];
    __shared__ float redf[8];
    __shared__ unsigned s_bin, s_k;

    const int tid = threadIdx.x;
    const float* row = at + (long long)blockIdx.x * SEQ;

    float4 vv = *(const float4*)(row + tid * 4);
    float v[4] = {vv.x, vv.y, vv.z, vv.w};
    unsigned u[4];
    float lmax = -3.402823466e38f;
    #pragma unroll
    for (int c = 0; c < 4; c++) {
        unsigned b = __float_as_uint(v[c]);
        u[c] = (b & 0x80000000u) ? ~b : (b | 0x80000000u);
        lmax = fmaxf(lmax, v[c]);
    }
    #pragma unroll
    for (int o = 16; o > 0; o >>= 1)
        lmax = fmaxf(lmax, __shfl_xor_sync(0xFFFFFFFFu, lmax, o));
    if ((tid & 31) == 0) redf[tid >> 5] = lmax;
    __syncthreads();
    if (tid < 32) {
        float m = (tid < 8) ? redf[tid] : -3.402823466e38f;
        #pragma unroll
        for (int o = 4; o > 0; o >>= 1)
            m = fmaxf(m, __shfl_xor_sync(0xFFFFFFFFu, m, o));
        if (tid == 0) redf[0] = m;
    }
    __syncthreads();
    const float m = redf[0];

    unsigned prefix = 0, k = KSEL;
    #pragma unroll
    for (int shift = 24; shift >= 0; shift -= 8) {
        hist[tid] = 0;
        __syncthreads();
        const unsigned himask = (shift == 24) ? 0u : (0xFFFFFFFFu << (shift + 8));
        #pragma unroll
        for (int c = 0; c < 4; c++)
            if ((u[c] & himask) == prefix)
                atomicAdd(&hist[(u[c] >> shift) & 255u], 1u);
        __syncthreads();
        if (tid < 32) {
            unsigned h[8], tot = 0;
            #pragma unroll
            for (int i = 0; i < 8; i++) { h[i] = hist[tid * 8 + i]; tot += h[i]; }
            unsigned s = tot;
            #pragma unroll
            for (int o = 1; o < 32; o <<= 1) {
                unsigned x = __shfl_down_sync(0xFFFFFFFFu, s, o);
                if (tid + o < 32) s += x;
            }
            unsigned run = s - tot;
            #pragma unroll
            for (int i = 7; i >= 0; i--) {
                unsigned greater = run;
                run += h[i];
                if (greater < k && k <= run) { s_bin = tid * 8 + i; s_k = k - greater; }
            }
        }
        __syncthreads();
        prefix |= s_bin << shift;
        k = s_k;
    }
    const unsigned thr_u = prefix;

    const float inv_t = 1.0f / 0.3f;
    float e[4];
    float lsum = 0.f;
    #pragma unroll
    for (int c = 0; c < 4; c++) {
        float adj = (u[c] >= thr_u) ? v[c] : -1e-7f;
        e[c] = __expf((adj - m) * inv_t);
        lsum += e[c];
    }
    #pragma unroll
    for (int o = 16; o > 0; o >>= 1)
        lsum += __shfl_xor_sync(0xFFFFFFFFu, lsum, o);
    if ((tid & 31) == 0) redf[tid >> 5] = lsum;
    __syncthreads();
    if (tid < 32) {
        float s = (tid < 8) ? redf[tid] : 0.f;
        #pragma unroll
        for (int o = 4; o > 0; o >>= 1)
            s += __shfl_xor_sync(0xFFFFFFFFu, s, o);
        if (tid == 0) redf[0] = s;
    }
    __syncthreads();
    const float inv_sum = 1.0f / redf[0];

    __nv_bfloat16 h[4], l[4];
    #pragma unroll
    for (int c = 0; c < 4; c++) {
        float p = e[c] * inv_sum;
        h[c] = bf_hi(p);
        l[c] = bf_lo(p, h[c]);
    }
    const long long i2 = (long long)blockIdx.x * (SEQ / 2) + tid * 2;
    ((__nv_bfloat162*)Ph)[i2]     = __halves2bfloat162(h[0], h[1]);
    ((__nv_bfloat162*)Ph)[i2 + 1] = __halves2bfloat162(h[2], h[3]);
    ((__nv_bfloat162*)Pl)[i2]     = __halves2bfloat162(l[0], l[1]);
    ((__nv_bfloat162*)Pl)[i2 + 1] = __halves2bfloat162(l[2], l[3]);
}

// ---------------- launch ----------------
extern "C" void kernel_launch(void* const* d_in, const int* in_sizes, int n_in,
                              void* d_out, int out_size)
{
    const float* h      = (const float*)d_in[0];
    const float* Wqk    = (const float*)d_in[1];
    const float* bqk    = (const float*)d_in[2];
    const float* weight = (const float*)d_in[3];
    const float* bias   = (const float*)d_in[4];
    float* out = (float*)d_out;

    __nv_bfloat16 *hh, *hl, *wqkTh, *wqkTl, *wTh, *wTl;
    __nv_bfloat16 *Qh, *Ql, *Kh, *Kl, *hWTh, *hWTl, *Ph, *Pl;
    float* at;
    cudaGetSymbolAddress((void**)&hh, g_hh);
    cudaGetSymbolAddress((void**)&hl, g_hl);
    cudaGetSymbolAddress((void**)&wqkTh, g_wqkTh);
    cudaGetSymbolAddress((void**)&wqkTl, g_wqkTl);
    cudaGetSymbolAddress((void**)&wTh, g_wTh);
    cudaGetSymbolAddress((void**)&wTl, g_wTl);
    cudaGetSymbolAddress((void**)&Qh, g_Qh);
    cudaGetSymbolAddress((void**)&Ql, g_Ql);
    cudaGetSymbolAddress((void**)&Kh, g_Kh);
    cudaGetSymbolAddress((void**)&Kl, g_Kl);
    cudaGetSymbolAddress((void**)&hWTh, g_hWTh);
    cudaGetSymbolAddress((void**)&hWTl, g_hWTl);
    cudaGetSymbolAddress((void**)&at, g_at);
    cudaGetSymbolAddress((void**)&Ph, g_Ph);
    cudaGetSymbolAddress((void**)&Pl, g_Pl);

    // stage = 30720B; 3-stage pipeline = 92160B; 2 CTAs/SM = 184KB <= 228KB
    const int SMB = 92160;
    cudaFuncSetAttribute(mm_gemm<0>, cudaFuncAttributeMaxDynamicSharedMemorySize, SMB);
    cudaFuncSetAttribute(mm_gemm<1>, cudaFuncAttributeMaxDynamicSharedMemorySize, SMB);
    cudaFuncSetAttribute(mm_gemm<2>, cudaFuncAttributeMaxDynamicSharedMemorySize, SMB);
    cudaFuncSetAttribute(mm_gemm<3>, cudaFuncAttributeMaxDynamicSharedMemorySize, SMB);

    const long long NF = (long long)SEQ * FDIM;
    const long long NN = (long long)SEQ * SEQ;

    // 0) splits
    split_kernel<<<(BATCH * SEQ * FDIM / 4 + 255) / 256, 256>>>(h, hh, hl,
                                                                BATCH * SEQ * FDIM / 4);
    transpose_split_kernel<<<dim3(PACK / 32, FDIM / 32), dim3(32, 8)>>>(
        Wqk, FDIM, PACK, wqkTh, wqkTl);
    transpose_split_kernel<<<dim3(FDIM / 32, FDIM / 32), dim3(32, 8)>>>(
        weight, FDIM, FDIM, wTh, wTl);

    // 1) proj: h @ Wqk (+bqk) fused even/odd split -> Q, K (K*0.125)
    mm_gemm<1><<<dim3(PACK / 64, BATCH * SEQ / 128, 1), 256, SMB>>>(
        hh, hl, 0, FDIM, wqkTh, wqkTl, 0, FDIM,
        nullptr, 0, 0, bqk, Qh, Ql, Kh, Kl, FDIM);

    // 2) hW = h @ weight -> hWT splits [b][320][1024]
    mm_gemm<2><<<dim3(FDIM / 64, BATCH * SEQ / 128, 1), 256, SMB>>>(
        hh, hl, 0, FDIM, wTh, wTl, 0, FDIM,
        nullptr, 0, 0, nullptr, hWTh, hWTl, nullptr, nullptr, FDIM);

    // 3) at[b] = Q[b] @ K[b]^T  (0.125 folded into K)
    mm_gemm<0><<<dim3(SEQ / 64, SEQ / 128, BATCH), 256, SMB>>>(
        Qh, Ql, NF, FDIM, Kh, Kl, NF, FDIM,
        at, NN, SEQ, nullptr, nullptr, nullptr, nullptr, nullptr, FDIM);

    // 4) top-171 threshold + softmax -> attn bf16 splits
    mask_softmax_kernel<<<BATCH * SEQ, 256>>>(at, Ph, Pl);

    // 5) out[b] = attn[b] @ hW[b] + bias
    mm_gemm<3><<<dim3(FDIM / 64, SEQ / 128, BATCH), 256, SMB>>>(
        Ph, Pl, NN, SEQ, hWTh, hWTl, NF, SEQ,
        out, 0, 0, bias, nullptr, nullptr, nullptr, nullptr, SEQ);
}